// round 12
// baseline (speedup 1.0000x reference)
#include <cuda_runtime.h>
#include <cuda_fp16.h>
#include <math.h>
#include <stdint.h>

#define DIMC 256
#define HEADS 8
#define TTOK 131072          // 32*4096 tokens
#define HIDD 1024

// ---------------- scratch (static __device__, no allocs) ----------------
// Swizzled 16KB tile images: tile = (row>>7)*(K/64) + (k>>6);
// byte = (row&127)*128 + ((((k&63)>>3) ^ (row&7))<<4) + (k&7)*2
__device__ __align__(128) __half g_xw  [(size_t)TTOK * DIMC];     // swizzled, K=256
__device__ __align__(128) __half g_qkv [(size_t)TTOK * 3 * DIMC]; // LINEAR (attn input)
__device__ __align__(128) __half g_attn[(size_t)TTOK * DIMC];     // swizzled, K=256
__device__ __align__(128) float  g_x1  [(size_t)TTOK * DIMC];     // linear fp32, window order
__device__ __align__(128) __half g_xn2 [(size_t)TTOK * DIMC];     // swizzled, K=256
__device__ __align__(128) __half g_h   [(size_t)TTOK * HIDD];     // swizzled, K=1024
__device__ __align__(128) __half g_wall[(3 * DIMC + DIMC + HIDD + DIMC) * DIMC + DIMC * HIDD];
__device__ float g_bias[HEADS * 64 * 64];

#define WOFF_QKV  0
#define WOFF_PROJ (3 * DIMC * DIMC)
#define WOFF_FC1  (WOFF_PROJ + DIMC * DIMC)
#define WOFF_FC2  (WOFF_FC1 + HIDD * DIMC)
#define WTOT      (WOFF_FC2 + DIMC * HIDD)

// ---------------- helpers ----------------
__device__ __forceinline__ uint32_t smem_u32(const void* p) {
    return (uint32_t)__cvta_generic_to_shared(p);
}
__device__ __forceinline__ void cp_async16(uint32_t saddr, const void* gptr) {
    asm volatile("cp.async.cg.shared.global [%0], [%1], 16;\n" :: "r"(saddr), "l"(gptr));
}
__device__ __forceinline__ void cp_commit() { asm volatile("cp.async.commit_group;\n"); }
__device__ __forceinline__ void bulk_g2s(uint32_t dst, const void* src, uint32_t bytes, uint32_t mbar) {
    asm volatile("cp.async.bulk.shared::cluster.global.mbarrier::complete_tx::bytes [%0], [%1], %2, [%3];"
                 :: "r"(dst), "l"(src), "r"(bytes), "r"(mbar) : "memory");
}
__device__ __forceinline__ void mbar_init(uint32_t mbar, uint32_t cnt) {
    asm volatile("mbarrier.init.shared.b64 [%0], %1;" :: "r"(mbar), "r"(cnt) : "memory");
}
__device__ __forceinline__ void mbar_expect_tx(uint32_t mbar, uint32_t bytes) {
    asm volatile("mbarrier.arrive.expect_tx.shared.b64 _, [%0], %1;" :: "r"(mbar), "r"(bytes) : "memory");
}
__device__ __forceinline__ void mbar_wait(uint32_t mbar, uint32_t parity) {
    asm volatile("{\n\t.reg .pred P1;\n\t"
                 "WAIT_%=:\n\t"
                 "mbarrier.try_wait.parity.acquire.cta.shared::cta.b64 P1, [%0], %1, 0x989680;\n\t"
                 "@P1 bra.uni DONE_%=;\n\t"
                 "bra.uni WAIT_%=;\n\t"
                 "DONE_%=:\n\t}"
                 :: "r"(mbar), "r"(parity) : "memory");
}
__device__ __forceinline__ void ldmatrix_x4(uint32_t& r0, uint32_t& r1, uint32_t& r2, uint32_t& r3, uint32_t addr) {
    asm volatile("ldmatrix.sync.aligned.m8n8.x4.shared.b16 {%0,%1,%2,%3}, [%4];\n"
                 : "=r"(r0), "=r"(r1), "=r"(r2), "=r"(r3) : "r"(addr));
}
__device__ __forceinline__ void ldmatrix_x2_trans(uint32_t& r0, uint32_t& r1, uint32_t addr) {
    asm volatile("ldmatrix.sync.aligned.m8n8.x2.trans.shared.b16 {%0,%1}, [%2];\n"
                 : "=r"(r0), "=r"(r1) : "r"(addr));
}
__device__ __forceinline__ void mma_f16acc(uint32_t c[2], const uint32_t a[4], const uint32_t b[2]) {
    asm volatile("mma.sync.aligned.m16n8k16.row.col.f16.f16.f16.f16 "
                 "{%0,%1}, {%2,%3,%4,%5}, {%6,%7}, {%0,%1};\n"
                 : "+r"(c[0]), "+r"(c[1])
                 : "r"(a[0]), "r"(a[1]), "r"(a[2]), "r"(a[3]), "r"(b[0]), "r"(b[1]));
}
__device__ __forceinline__ void mma_f32acc(float c[4], const uint32_t a[4], const uint32_t b[2]) {
    asm volatile("mma.sync.aligned.m16n8k16.row.col.f32.f16.f16.f32 "
                 "{%0,%1,%2,%3}, {%4,%5,%6,%7}, {%8,%9}, {%0,%1,%2,%3};\n"
                 : "+f"(c[0]), "+f"(c[1]), "+f"(c[2]), "+f"(c[3])
                 : "r"(a[0]), "r"(a[1]), "r"(a[2]), "r"(a[3]), "r"(b[0]), "r"(b[1]));
}
__device__ __forceinline__ float gelu_f(float v) {
    return 0.5f * v * (1.0f + erff(v * 0.7071067811865476f));
}
__device__ __forceinline__ int orig_to_win(int t) {
    int b = t >> 12, rem = t & 4095;
    int r = rem >> 6, c = rem & 63;
    int wi = (b << 6) + ((r >> 3) << 3) + (c >> 3);
    return (wi << 6) + ((r & 7) << 3) + (c & 7);
}
__device__ __forceinline__ int win_to_orig(int tw) {
    int wi = tw >> 6, k = tw & 63;
    int b = wi >> 6, w64 = wi & 63;
    int r = ((w64 >> 3) << 3) + (k >> 3);
    int c = ((w64 & 7) << 3) + (k & 7);
    return (b << 12) + (r << 6) + c;
}
__device__ __forceinline__ size_t swz_off(int row, int k, int Kd) {
    return ((size_t)((row >> 7) * (Kd >> 6) + (k >> 6)) << 14)
         + (size_t)((row & 127) * 128 + ((((k & 63) >> 3) ^ (row & 7)) << 4) + (k & 7) * 2);
}

// ---------------- fused weight convert -> swizzled fp16 tiles ----------------
__global__ void cvt_all_kernel(const float* __restrict__ wqkv, const float* __restrict__ wproj,
                               const float* __restrict__ wfc1, const float* __restrict__ wfc2,
                               __half* __restrict__ out) {
    int i = blockIdx.x * blockDim.x + threadIdx.x;
    int li = i * 8;
    const float* src; size_t basebyte; int Kd; int loc;
    if (li < WOFF_PROJ)      { src = wqkv;  loc = li;             basebyte = 0;                    Kd = 256; }
    else if (li < WOFF_FC1)  { src = wproj; loc = li - WOFF_PROJ; basebyte = (size_t)WOFF_PROJ*2;  Kd = 256; }
    else if (li < WOFF_FC2)  { src = wfc1;  loc = li - WOFF_FC1;  basebyte = (size_t)WOFF_FC1*2;   Kd = 256; }
    else                     { src = wfc2;  loc = li - WOFF_FC2;  basebyte = (size_t)WOFF_FC2*2;   Kd = 1024; }
    float4 a = *(const float4*)(src + loc);
    float4 b = *(const float4*)(src + loc + 4);
    int row = loc / Kd, k = loc % Kd;
    size_t off = basebyte + swz_off(row, k, Kd);
    __half2 p0 = __floats2half2_rn(a.x, a.y);
    __half2 p1 = __floats2half2_rn(a.z, a.w);
    __half2 p2 = __floats2half2_rn(b.x, b.y);
    __half2 p3 = __floats2half2_rn(b.z, b.w);
    uint4 pk;
    pk.x = *(uint32_t*)&p0; pk.y = *(uint32_t*)&p1; pk.z = *(uint32_t*)&p2; pk.w = *(uint32_t*)&p3;
    *(uint4*)((char*)out + off) = pk;
}

// ---------------- bias table precompute: g_bias[h][n][m] ----------------
__global__ void bias_kernel(const float* __restrict__ btab, float* __restrict__ bout) {
    int t = blockIdx.x * blockDim.x + threadIdx.x;
    int m = t & 63, n = (t >> 6) & 63, h = t >> 12;
    int rel = ((n >> 3) - (m >> 3) + 7) * 15 + ((n & 7) - (m & 7) + 7);
    bout[t] = btab[rel * 8 + h];
}

// ---------------- LayerNorm1 (warp per token) -> swizzled fp16 out (K=256) ----------------
__global__ __launch_bounds__(256) void ln_kernel(const float* __restrict__ x,
                                                 const float* __restrict__ g,
                                                 const float* __restrict__ b,
                                                 __half* __restrict__ out) {
    int warp = (blockIdx.x * 256 + threadIdx.x) >> 5;
    int lane = threadIdx.x & 31;
    const float* row = x + (size_t)warp * DIMC + lane * 8;
    float4 v0 = *(const float4*)row;
    float4 v1 = *(const float4*)(row + 4);
    float s = (v0.x + v0.y) + (v0.z + v0.w) + ((v1.x + v1.y) + (v1.z + v1.w));
#pragma unroll
    for (int o = 16; o; o >>= 1) s += __shfl_xor_sync(0xffffffffu, s, o);
    float mu = s * (1.0f / 256.0f);
    float d[8] = { v0.x - mu, v0.y - mu, v0.z - mu, v0.w - mu,
                   v1.x - mu, v1.y - mu, v1.z - mu, v1.w - mu };
    float ss = 0.f;
#pragma unroll
    for (int i = 0; i < 8; i++) ss += d[i] * d[i];
#pragma unroll
    for (int o = 16; o; o >>= 1) ss += __shfl_xor_sync(0xffffffffu, ss, o);
    float rstd = rsqrtf(ss * (1.0f / 256.0f) + 1e-5f);
    float4 gg0 = *(const float4*)(g + lane * 8);
    float4 gg1 = *(const float4*)(g + lane * 8 + 4);
    float4 bb0 = *(const float4*)(b + lane * 8);
    float4 bb1 = *(const float4*)(b + lane * 8 + 4);
    float y[8];
    y[0] = d[0] * rstd * gg0.x + bb0.x;  y[1] = d[1] * rstd * gg0.y + bb0.y;
    y[2] = d[2] * rstd * gg0.z + bb0.z;  y[3] = d[3] * rstd * gg0.w + bb0.w;
    y[4] = d[4] * rstd * gg1.x + bb1.x;  y[5] = d[5] * rstd * gg1.y + bb1.y;
    y[6] = d[6] * rstd * gg1.z + bb1.z;  y[7] = d[7] * rstd * gg1.w + bb1.w;
    int orow = orig_to_win(warp);
    __half2 p0 = __floats2half2_rn(y[0], y[1]);
    __half2 p1 = __floats2half2_rn(y[2], y[3]);
    __half2 p2 = __floats2half2_rn(y[4], y[5]);
    __half2 p3 = __floats2half2_rn(y[6], y[7]);
    uint4 pk;
    pk.x = *(uint32_t*)&p0; pk.y = *(uint32_t*)&p1; pk.z = *(uint32_t*)&p2; pk.w = *(uint32_t*)&p3;
    *(uint4*)((char*)out + swz_off(orow, lane * 8, 256)) = pk;
}

// ---------------- fp16 TN GEMM (f16 accumulate), bulk tile loads ----------------
// Tile 128x128, 8 warps (4M x 2N), warp tile 32x64, 3-stage ring, 2 CTAs/SM.
// EPI 0: qkv (+bias -> fp16 LINEAR out, stride 768)
// EPI 2: fc1 (+bias, GELU -> fp16 SWIZZLED out, K=1024 image)
// EPI 3: fc2 (+bias, +residual x1(win) -> fp32 out scattered to orig order)
#define STG 32768
#define GSMEM (3 * STG + 64)

template<int N, int K, int EPI>
__global__ __launch_bounds__(256, 2) void gemm_kernel(const __half* __restrict__ A,
                                                      const __half* __restrict__ Bw,
                                                      const float* __restrict__ bias,
                                                      const float* __restrict__ res,
                                                      float* __restrict__ outf,
                                                      __half* __restrict__ outb) {
    extern __shared__ __align__(128) uint8_t dynsm[];
    const int tid = threadIdx.x;
    const int lane = tid & 31;
    const int wid = tid >> 5;
    const int wm = wid & 3;
    const int wn = wid >> 2;
    const int m0 = blockIdx.x * 128;
    const int n0 = blockIdx.y * 128;
    const uint32_t sbase = smem_u32(dynsm);
    const uint32_t mb = sbase + 3 * STG;
    constexpr int KT = K / 64;

    if (tid == 0) { mbar_init(mb, 1); mbar_init(mb + 8, 1); mbar_init(mb + 16, 1); }
    __syncthreads();

    auto issue = [&](int kt) {
        uint32_t s = (uint32_t)(kt % 3);
        uint32_t mbs = mb + s * 8;
        mbar_expect_tx(mbs, 32768u);
        const char* srcA = (const char*)A + ((size_t)blockIdx.x * KT + kt) * 16384;
        const char* srcB = (const char*)Bw + ((size_t)blockIdx.y * KT + kt) * 16384;
        bulk_g2s(sbase + s * STG, srcA, 16384u, mbs);
        bulk_g2s(sbase + s * STG + 16384u, srcB, 16384u, mbs);
    };
    if (tid == 0) { issue(0); issue(1); }

    uint32_t acc[2][8][2];
#pragma unroll
    for (int a = 0; a < 2; a++)
#pragma unroll
        for (int bq = 0; bq < 8; bq++) { acc[a][bq][0] = 0u; acc[a][bq][1] = 0u; }

    const int ti = lane >> 3, rr = lane & 7;
#pragma unroll 1
    for (int kt = 0; kt < KT; kt++) {
        __syncthreads();
        if (tid == 0 && kt + 2 < KT) issue(kt + 2);
        mbar_wait(mb + (uint32_t)(kt % 3) * 8, (uint32_t)((kt / 3) & 1));
        uint32_t abase = sbase + (uint32_t)(kt % 3) * STG;
        uint32_t bbase = abase + 16384;
#pragma unroll
        for (int ks = 0; ks < 4; ks++) {
            int kcb = ks * 2;
            uint32_t afr[2][4];
#pragma unroll
            for (int mt = 0; mt < 2; mt++) {
                int row = wm * 32 + mt * 16 + ((ti & 1) ? 8 : 0) + rr;
                int kc = kcb + (ti >> 1);
                uint32_t addr = abase + ((((uint32_t)row << 3) | (uint32_t)(kc ^ (row & 7))) << 4);
                ldmatrix_x4(afr[mt][0], afr[mt][1], afr[mt][2], afr[mt][3], addr);
            }
            uint32_t bfr[8][2];
#pragma unroll
            for (int ng = 0; ng < 4; ng++) {
                int row = wn * 64 + ng * 16 + ((ti >> 1) ? 8 : 0) + rr;
                int kc = kcb + (ti & 1);
                uint32_t addr = bbase + ((((uint32_t)row << 3) | (uint32_t)(kc ^ (row & 7))) << 4);
                uint32_t r0, r1, r2, r3;
                ldmatrix_x4(r0, r1, r2, r3, addr);
                bfr[2 * ng][0] = r0;     bfr[2 * ng][1] = r1;
                bfr[2 * ng + 1][0] = r2; bfr[2 * ng + 1][1] = r3;
            }
#pragma unroll
            for (int mt = 0; mt < 2; mt++)
#pragma unroll
                for (int nt = 0; nt < 8; nt++)
                    mma_f16acc(acc[mt][nt], afr[mt], bfr[nt]);
        }
    }

    int lrow = lane >> 2, lc2 = (lane & 3) * 2;
#pragma unroll
    for (int mt = 0; mt < 2; mt++) {
#pragma unroll
        for (int hh = 0; hh < 2; hh++) {
            int r = m0 + wm * 32 + mt * 16 + lrow + hh * 8;
            if constexpr (EPI == 0) {
                __half* op = outb + (size_t)r * N;
#pragma unroll
                for (int nt = 0; nt < 8; nt++) {
                    int c = n0 + wn * 64 + nt * 8 + lc2;
                    float2 bb = *(const float2*)(bias + c);
                    float2 cv = __half22float2(*(__half2*)&acc[mt][nt][hh]);
                    *(__half2*)(op + c) = __floats2half2_rn(cv.x + bb.x, cv.y + bb.y);
                }
            } else if constexpr (EPI == 2) {
#pragma unroll
                for (int nt = 0; nt < 8; nt++) {
                    int c = n0 + wn * 64 + nt * 8 + lc2;
                    float2 bb = *(const float2*)(bias + c);
                    float2 cv = __half22float2(*(__half2*)&acc[mt][nt][hh]);
                    *(__half2*)((char*)outb + swz_off(r, c, 1024)) =
                        __floats2half2_rn(gelu_f(cv.x + bb.x), gelu_f(cv.y + bb.y));
                }
            } else {
                int torig = win_to_orig(r);
                const float* x1r = res + (size_t)r * 256;
                float* op = outf + (size_t)torig * 256;
#pragma unroll
                for (int nt = 0; nt < 8; nt++) {
                    int c = n0 + wn * 64 + nt * 8 + lc2;
                    float2 bb = *(const float2*)(bias + c);
                    float2 cv = __half22float2(*(__half2*)&acc[mt][nt][hh]);
                    float2 rr2 = *(const float2*)(x1r + c);
                    *(float2*)(op + c) = make_float2(rr2.x + cv.x + bb.x, rr2.y + cv.y + bb.y);
                }
            }
        }
    }
}

// ---------------- proj GEMM (BN=256, fused residual + LN2) ----------------
// Tile 128x256, 8 warps (2M x 4N), warp tile 64x64, 2-stage bulk ring (96KB), 2 CTAs/SM.
// Epilogue: x1 = x[orig] + acc + bias (two 64-row smem half-passes), LN2 -> xn2 swizzled.
#define PSTG 49152           // A 16KB + B 32KB
#define PSMEM (2 * PSTG + 64)
#define LNP 260

__global__ __launch_bounds__(256, 2) void proj_kernel(const __half* __restrict__ A,
                                                      const __half* __restrict__ Bw,
                                                      const float* __restrict__ bias,
                                                      const float* __restrict__ xres,
                                                      const float* __restrict__ g2,
                                                      const float* __restrict__ b2,
                                                      float* __restrict__ x1out,
                                                      __half* __restrict__ xn2out) {
    extern __shared__ __align__(128) uint8_t dynsm[];
    const int tid = threadIdx.x;
    const int lane = tid & 31;
    const int wid = tid >> 5;
    const int wm = wid & 1;      // 2 warps along M (64 rows)
    const int wn = wid >> 1;     // 4 warps along N (64 cols)
    const int m0 = blockIdx.x * 128;
    const uint32_t sbase = smem_u32(dynsm);
    const uint32_t mb = sbase + 2 * PSTG;
    constexpr int KT = 4;        // K = 256

    if (tid == 0) { mbar_init(mb, 1); mbar_init(mb + 8, 1); }
    __syncthreads();

    auto issue = [&](int kt) {
        uint32_t s = (uint32_t)(kt & 1);
        uint32_t mbs = mb + s * 8;
        mbar_expect_tx(mbs, 49152u);
        const char* srcA = (const char*)A + ((size_t)blockIdx.x * KT + kt) * 16384;
        bulk_g2s(sbase + s * PSTG, srcA, 16384u, mbs);
        // B: 256 rows -> two row-block tiles
        bulk_g2s(sbase + s * PSTG + 16384u,
                 (const char*)Bw + ((size_t)0 * KT + kt) * 16384, 16384u, mbs);
        bulk_g2s(sbase + s * PSTG + 32768u,
                 (const char*)Bw + ((size_t)1 * KT + kt) * 16384, 16384u, mbs);
    };
    if (tid == 0) { issue(0); issue(1); }

    uint32_t acc[4][8][2];
#pragma unroll
    for (int a = 0; a < 4; a++)
#pragma unroll
        for (int bq = 0; bq < 8; bq++) { acc[a][bq][0] = 0u; acc[a][bq][1] = 0u; }

    const int ti = lane >> 3, rr = lane & 7;
#pragma unroll 1
    for (int kt = 0; kt < KT; kt++) {
        mbar_wait(mb + (uint32_t)(kt & 1) * 8, (uint32_t)((kt >> 1) & 1));
        uint32_t abase = sbase + (uint32_t)(kt & 1) * PSTG;
        uint32_t bbase = abase + 16384;
#pragma unroll
        for (int ks = 0; ks < 4; ks++) {
            int kcb = ks * 2;
            uint32_t afr[4][4];
#pragma unroll
            for (int mt = 0; mt < 4; mt++) {
                int row = wm * 64 + mt * 16 + ((ti & 1) ? 8 : 0) + rr;
                int kc = kcb + (ti >> 1);
                uint32_t addr = abase + ((((uint32_t)row << 3) | (uint32_t)(kc ^ (row & 7))) << 4);
                ldmatrix_x4(afr[mt][0], afr[mt][1], afr[mt][2], afr[mt][3], addr);
            }
            uint32_t bfr[8][2];
#pragma unroll
            for (int ng = 0; ng < 4; ng++) {
                int row = wn * 64 + ng * 16 + ((ti >> 1) ? 8 : 0) + rr;
                int kc = kcb + (ti & 1);
                uint32_t addr = bbase + ((uint32_t)(row >> 7) << 14)
                              + ((((uint32_t)(row & 127) << 3) | (uint32_t)(kc ^ (row & 7))) << 4);
                uint32_t r0, r1, r2, r3;
                ldmatrix_x4(r0, r1, r2, r3, addr);
                bfr[2 * ng][0] = r0;     bfr[2 * ng][1] = r1;
                bfr[2 * ng + 1][0] = r2; bfr[2 * ng + 1][1] = r3;
            }
#pragma unroll
            for (int mt = 0; mt < 4; mt++)
#pragma unroll
                for (int nt = 0; nt < 8; nt++)
                    mma_f16acc(acc[mt][nt], afr[mt], bfr[nt]);
        }
        __syncthreads();
        if (tid == 0 && kt + 2 < KT) issue(kt + 2);
    }

    // -------- epilogue: residual + LN2, two 64-row half-passes --------
    float* stg = (float*)dynsm;
    int lrow = lane >> 2, lc2 = (lane & 3) * 2;
    float4 gg0 = *(const float4*)(g2 + lane * 8);
    float4 gg1 = *(const float4*)(g2 + lane * 8 + 4);
    float4 bb0 = *(const float4*)(b2 + lane * 8);
    float4 bb1 = *(const float4*)(b2 + lane * 8 + 4);

#pragma unroll 1
    for (int half = 0; half < 2; half++) {
        if (wm == half) {
#pragma unroll
            for (int mt = 0; mt < 4; mt++) {
#pragma unroll
                for (int hh = 0; hh < 2; hh++) {
                    int rloc = wm * 64 + mt * 16 + lrow + hh * 8;
                    int torig = win_to_orig(m0 + rloc);
                    const float* xr = xres + (size_t)torig * 256;
                    float* srow = stg + (rloc - half * 64) * LNP;
#pragma unroll
                    for (int nt = 0; nt < 8; nt++) {
                        int c = wn * 64 + nt * 8 + lc2;
                        float2 bb = *(const float2*)(bias + c);
                        float2 cv = __half22float2(*(__half2*)&acc[mt][nt][hh]);
                        float2 xv = *(const float2*)(xr + c);
                        srow[c]     = xv.x + cv.x + bb.x;
                        srow[c + 1] = xv.y + cv.y + bb.y;
                    }
                }
            }
        }
        __syncthreads();
        // LN over the 64 staged rows: warp handles 8 rows
#pragma unroll 1
        for (int j = 0; j < 8; j++) {
            int lr = wid * 8 + j;
            const float* rw = stg + lr * LNP + lane * 8;
            float4 v0 = *(const float4*)rw;
            float4 v1 = *(const float4*)(rw + 4);
            float s = (v0.x + v0.y) + (v0.z + v0.w) + ((v1.x + v1.y) + (v1.z + v1.w));
#pragma unroll
            for (int o = 16; o; o >>= 1) s += __shfl_xor_sync(0xffffffffu, s, o);
            float mu = s * (1.0f / 256.0f);
            float d[8] = { v0.x - mu, v0.y - mu, v0.z - mu, v0.w - mu,
                           v1.x - mu, v1.y - mu, v1.z - mu, v1.w - mu };
            float ss = 0.f;
#pragma unroll
            for (int i2 = 0; i2 < 8; i2++) ss += d[i2] * d[i2];
#pragma unroll
            for (int o = 16; o; o >>= 1) ss += __shfl_xor_sync(0xffffffffu, ss, o);
            float rstd = rsqrtf(ss * (1.0f / 256.0f) + 1e-5f);
            int grow = m0 + half * 64 + lr;
            float* x1r = x1out + (size_t)grow * 256 + lane * 8;
            *(float4*)x1r = v0;
            *(float4*)(x1r + 4) = v1;
            float y[8];
            y[0] = d[0] * rstd * gg0.x + bb0.x;  y[1] = d[1] * rstd * gg0.y + bb0.y;
            y[2] = d[2] * rstd * gg0.z + bb0.z;  y[3] = d[3] * rstd * gg0.w + bb0.w;
            y[4] = d[4] * rstd * gg1.x + bb1.x;  y[5] = d[5] * rstd * gg1.y + bb1.y;
            y[6] = d[6] * rstd * gg1.z + bb1.z;  y[7] = d[7] * rstd * gg1.w + bb1.w;
            __half2 p0 = __floats2half2_rn(y[0], y[1]);
            __half2 p1 = __floats2half2_rn(y[2], y[3]);
            __half2 p2 = __floats2half2_rn(y[4], y[5]);
            __half2 p3 = __floats2half2_rn(y[6], y[7]);
            uint4 pk;
            pk.x = *(uint32_t*)&p0; pk.y = *(uint32_t*)&p1;
            pk.z = *(uint32_t*)&p2; pk.w = *(uint32_t*)&p3;
            *(uint4*)((char*)xn2out + swz_off(grow, lane * 8, 256)) = pk;
        }
        __syncthreads();
    }
}

// ---------------- windowed attention: fp16 in, f32 accum; swizzled fp16 out ----------------
#define ATT_PITCH 1552
#define ATT_SMEM (64 * ATT_PITCH)

__global__ __launch_bounds__(256, 2) void attn_kernel(const __half* __restrict__ qkv,
                                                      const float* __restrict__ bias_pre,
                                                      __half* __restrict__ out) {
    extern __shared__ __align__(128) uint8_t dynsm[];
    const int w = blockIdx.x;
    const int tid = threadIdx.x;
    const int h = tid >> 5, lane = tid & 31;
    const uint32_t sb = smem_u32(dynsm);
    const __half* gw = qkv + (size_t)w * 49152;

#pragma unroll
    for (int i = 0; i < 24; i++) {
        int ch = tid + i * 256;
        int r = ch / 96, c = ch % 96;
        cp_async16(sb + (uint32_t)(r * ATT_PITCH + c * 16), gw + r * 768 + c * 8);
    }
    cp_commit();
    asm volatile("cp.async.wait_group 0;\n" ::: "memory");
    __syncthreads();

    const uint32_t qbase = sb + (uint32_t)(h * 32) * 2;
    const uint32_t kbase = sb + (uint32_t)(256 + h * 32) * 2;
    const uint32_t vbase = sb + (uint32_t)(512 + h * 32) * 2;
    const float* bp = bias_pre + h * 4096;
    const float scale = 0.17677669529663688f;
    const int ti = lane >> 3, rr = lane & 7;
    const int lq = lane >> 2, lc = (lane & 3) * 2;

#pragma unroll 1
    for (int i = 0; i < 4; i++) {
        uint32_t qf[2][4];
#pragma unroll
        for (int ks = 0; ks < 2; ks++) {
            int row = i * 16 + ((ti & 1) ? 8 : 0) + rr;
            uint32_t addr = qbase + (uint32_t)(row * ATT_PITCH) + (uint32_t)((ks * 2 + (ti >> 1)) * 16);
            ldmatrix_x4(qf[ks][0], qf[ks][1], qf[ks][2], qf[ks][3], addr);
        }
        float sacc[8][4];
#pragma unroll
        for (int j = 0; j < 8; j++)
#pragma unroll
            for (int c = 0; c < 4; c++) sacc[j][c] = 0.f;
#pragma unroll
        for (int ks = 0; ks < 2; ks++) {
#pragma unroll
            for (int ng = 0; ng < 4; ng++) {
                int row = ng * 16 + ((ti >> 1) ? 8 : 0) + rr;
                uint32_t addr = kbase + (uint32_t)(row * ATT_PITCH) + (uint32_t)((ks * 2 + (ti & 1)) * 16);
                uint32_t b0, b1, b2, b3;
                ldmatrix_x4(b0, b1, b2, b3, addr);
                uint32_t bf0[2] = { b0, b1 }, bf1[2] = { b2, b3 };
                mma_f32acc(sacc[2 * ng],     qf[ks], bf0);
                mma_f32acc(sacc[2 * ng + 1], qf[ks], bf1);
            }
        }
        int r0 = i * 16 + lq, r1 = r0 + 8;
        float p[8][4];
        float mx0 = -1e30f, mx1 = -1e30f;
#pragma unroll
        for (int j = 0; j < 8; j++) {
            float2 b0 = *(const float2*)(bp + r0 * 64 + j * 8 + lc);
            float2 b1 = *(const float2*)(bp + r1 * 64 + j * 8 + lc);
            p[j][0] = fmaf(sacc[j][0], scale, b0.x);
            p[j][1] = fmaf(sacc[j][1], scale, b0.y);
            p[j][2] = fmaf(sacc[j][2], scale, b1.x);
            p[j][3] = fmaf(sacc[j][3], scale, b1.y);
            mx0 = fmaxf(mx0, fmaxf(p[j][0], p[j][1]));
            mx1 = fmaxf(mx1, fmaxf(p[j][2], p[j][3]));
        }
        mx0 = fmaxf(mx0, __shfl_xor_sync(0xffffffffu, mx0, 1));
        mx0 = fmaxf(mx0, __shfl_xor_sync(0xffffffffu, mx0, 2));
        mx1 = fmaxf(mx1, __shfl_xor_sync(0xffffffffu, mx1, 1));
        mx1 = fmaxf(mx1, __shfl_xor_sync(0xffffffffu, mx1, 2));
        float sm0 = 0.f, sm1 = 0.f;
#pragma unroll
        for (int j = 0; j < 8; j++) {
            p[j][0] = __expf(p[j][0] - mx0);
            p[j][1] = __expf(p[j][1] - mx0);
            p[j][2] = __expf(p[j][2] - mx1);
            p[j][3] = __expf(p[j][3] - mx1);
            sm0 += p[j][0] + p[j][1];
            sm1 += p[j][2] + p[j][3];
        }
        sm0 += __shfl_xor_sync(0xffffffffu, sm0, 1);
        sm0 += __shfl_xor_sync(0xffffffffu, sm0, 2);
        sm1 += __shfl_xor_sync(0xffffffffu, sm1, 1);
        sm1 += __shfl_xor_sync(0xffffffffu, sm1, 2);
        float inv0 = 1.0f / sm0, inv1 = 1.0f / sm1;

        uint32_t ap[4][4];
#pragma unroll
        for (int ks = 0; ks < 4; ks++) {
            __half2 t0 = __floats2half2_rn(p[2 * ks][0],     p[2 * ks][1]);
            __half2 t1 = __floats2half2_rn(p[2 * ks][2],     p[2 * ks][3]);
            __half2 t2 = __floats2half2_rn(p[2 * ks + 1][0], p[2 * ks + 1][1]);
            __half2 t3 = __floats2half2_rn(p[2 * ks + 1][2], p[2 * ks + 1][3]);
            ap[ks][0] = *(uint32_t*)&t0; ap[ks][1] = *(uint32_t*)&t1;
            ap[ks][2] = *(uint32_t*)&t2; ap[ks][3] = *(uint32_t*)&t3;
        }
        float o[4][4];
#pragma unroll
        for (int jj = 0; jj < 4; jj++)
#pragma unroll
            for (int c = 0; c < 4; c++) o[jj][c] = 0.f;
#pragma unroll
        for (int ks = 0; ks < 4; ks++) {
#pragma unroll
            for (int jj = 0; jj < 4; jj++) {
                uint32_t bv[2];
                uint32_t addr = vbase + (uint32_t)((ks * 16 + (lane & 15)) * ATT_PITCH) + (uint32_t)(jj * 16);
                ldmatrix_x2_trans(bv[0], bv[1], addr);
                mma_f32acc(o[jj], ap[ks], bv);
            }
        }
        int row0 = w * 64 + r0, row1 = w * 64 + r1;
#pragma unroll
        for (int jj = 0; jj < 4; jj++) {
            int k = h * 32 + jj * 8 + lc;
            *(__half2*)((char*)out + swz_off(row0, k, 256)) =
                __floats2half2_rn(o[jj][0] * inv0, o[jj][1] * inv0);
            *(__half2*)((char*)out + swz_off(row1, k, 256)) =
                __floats2half2_rn(o[jj][2] * inv1, o[jj][3] * inv1);
        }
    }
}

// ---------------- launch ----------------
extern "C" void kernel_launch(void* const* d_in, const int* in_sizes, int n_in,
                              void* d_out, int out_size) {
    const float* x      = (const float*)d_in[0];
    const float* g1     = (const float*)d_in[2];
    const float* b1     = (const float*)d_in[3];
    const float* w_qkv  = (const float*)d_in[4];
    const float* b_qkv  = (const float*)d_in[5];
    const float* btab   = (const float*)d_in[6];
    const float* w_proj = (const float*)d_in[7];
    const float* b_proj = (const float*)d_in[8];
    const float* g2     = (const float*)d_in[9];
    const float* b2     = (const float*)d_in[10];
    const float* w_fc1  = (const float*)d_in[11];
    const float* b_fc1  = (const float*)d_in[12];
    const float* w_fc2  = (const float*)d_in[13];
    const float* b_fc2  = (const float*)d_in[14];
    float* out = (float*)d_out;

    __half *xw, *qkv, *attn, *xn2, *hbuf, *wall;
    float *x1, *bpre;
    cudaGetSymbolAddress((void**)&xw,   g_xw);
    cudaGetSymbolAddress((void**)&qkv,  g_qkv);
    cudaGetSymbolAddress((void**)&attn, g_attn);
    cudaGetSymbolAddress((void**)&x1,   g_x1);
    cudaGetSymbolAddress((void**)&xn2,  g_xn2);
    cudaGetSymbolAddress((void**)&hbuf, g_h);
    cudaGetSymbolAddress((void**)&wall, g_wall);
    cudaGetSymbolAddress((void**)&bpre, g_bias);

    __half* wq = wall + WOFF_QKV;
    __half* wp = wall + WOFF_PROJ;
    __half* w1 = wall + WOFF_FC1;
    __half* w2 = wall + WOFF_FC2;

    cudaFuncSetAttribute(gemm_kernel<768, 256, 0>,  cudaFuncAttributeMaxDynamicSharedMemorySize, GSMEM);
    cudaFuncSetAttribute(gemm_kernel<1024, 256, 2>, cudaFuncAttributeMaxDynamicSharedMemorySize, GSMEM);
    cudaFuncSetAttribute(gemm_kernel<256, 1024, 3>, cudaFuncAttributeMaxDynamicSharedMemorySize, GSMEM);
    cudaFuncSetAttribute(proj_kernel, cudaFuncAttributeMaxDynamicSharedMemorySize, PSMEM);
    cudaFuncSetAttribute(attn_kernel, cudaFuncAttributeMaxDynamicSharedMemorySize, ATT_SMEM);

    cvt_all_kernel<<<WTOT / 8 / 256, 256>>>(w_qkv, w_proj, w_fc1, w_fc2, wall);
    bias_kernel<<<HEADS * 64 * 64 / 256, 256>>>(btab, bpre);
    ln_kernel<<<TTOK / 8, 256>>>(x, g1, b1, xw);
    gemm_kernel<768, 256, 0><<<dim3(TTOK / 128, 6), 256, GSMEM>>>(
        xw, wq, b_qkv, nullptr, nullptr, qkv);
    attn_kernel<<<2048, 256, ATT_SMEM>>>(qkv, bpre, attn);
    proj_kernel<<<TTOK / 128, 256, PSMEM>>>(attn, wp, b_proj, x, g2, b2, x1, xn2);
    gemm_kernel<1024, 256, 2><<<dim3(TTOK / 128, 8), 256, GSMEM>>>(
        xn2, w1, b_fc1, nullptr, nullptr, hbuf);
    gemm_kernel<256, 1024, 3><<<dim3(TTOK / 128, 2), 256, GSMEM>>>(
        hbuf, w2, b_fc2, x1, out, nullptr);
}

// round 13
// speedup vs baseline: 1.1071x; 1.1071x over previous
#include <cuda_runtime.h>
#include <cuda_fp16.h>
#include <math.h>
#include <stdint.h>

#define DIMC 256
#define HEADS 8
#define TTOK 131072          // 32*4096 tokens
#define HIDD 1024

// ---------------- scratch (static __device__, no allocs) ----------------
// Swizzled 16KB tile images: tile = (row>>7)*(K/64) + (k>>6);
// byte = (row&127)*128 + ((((k&63)>>3) ^ (row&7))<<4) + (k&7)*2
__device__ __align__(128) __half g_xw  [(size_t)TTOK * DIMC];     // swizzled, K=256
__device__ __align__(128) __half g_qkv [(size_t)TTOK * 3 * DIMC]; // LINEAR (attn input)
__device__ __align__(128) __half g_attn[(size_t)TTOK * DIMC];     // swizzled, K=256
__device__ __align__(128) float  g_x1  [(size_t)TTOK * DIMC];     // linear fp32, window order
__device__ __align__(128) __half g_xn2 [(size_t)TTOK * DIMC];     // swizzled, K=256
__device__ __align__(128) __half g_h   [(size_t)TTOK * HIDD];     // swizzled, K=1024
__device__ __align__(128) __half g_wall[(3 * DIMC + DIMC + HIDD + DIMC) * DIMC + DIMC * HIDD];
__device__ float g_bias[HEADS * 64 * 64];

#define WOFF_QKV  0
#define WOFF_PROJ (3 * DIMC * DIMC)
#define WOFF_FC1  (WOFF_PROJ + DIMC * DIMC)
#define WOFF_FC2  (WOFF_FC1 + HIDD * DIMC)
#define WTOT      (WOFF_FC2 + DIMC * HIDD)

// ---------------- helpers ----------------
__device__ __forceinline__ uint32_t smem_u32(const void* p) {
    return (uint32_t)__cvta_generic_to_shared(p);
}
__device__ __forceinline__ void cp_async16(uint32_t saddr, const void* gptr) {
    asm volatile("cp.async.cg.shared.global [%0], [%1], 16;\n" :: "r"(saddr), "l"(gptr));
}
__device__ __forceinline__ void cp_commit() { asm volatile("cp.async.commit_group;\n"); }
__device__ __forceinline__ void bulk_g2s(uint32_t dst, const void* src, uint32_t bytes, uint32_t mbar) {
    asm volatile("cp.async.bulk.shared::cluster.global.mbarrier::complete_tx::bytes [%0], [%1], %2, [%3];"
                 :: "r"(dst), "l"(src), "r"(bytes), "r"(mbar) : "memory");
}
__device__ __forceinline__ void mbar_init(uint32_t mbar, uint32_t cnt) {
    asm volatile("mbarrier.init.shared.b64 [%0], %1;" :: "r"(mbar), "r"(cnt) : "memory");
}
__device__ __forceinline__ void mbar_expect_tx(uint32_t mbar, uint32_t bytes) {
    asm volatile("mbarrier.arrive.expect_tx.shared.b64 _, [%0], %1;" :: "r"(mbar), "r"(bytes) : "memory");
}
__device__ __forceinline__ void mbar_wait(uint32_t mbar, uint32_t parity) {
    asm volatile("{\n\t.reg .pred P1;\n\t"
                 "WAIT_%=:\n\t"
                 "mbarrier.try_wait.parity.acquire.cta.shared::cta.b64 P1, [%0], %1, 0x989680;\n\t"
                 "@P1 bra.uni DONE_%=;\n\t"
                 "bra.uni WAIT_%=;\n\t"
                 "DONE_%=:\n\t}"
                 :: "r"(mbar), "r"(parity) : "memory");
}
__device__ __forceinline__ void ldmatrix_x4(uint32_t& r0, uint32_t& r1, uint32_t& r2, uint32_t& r3, uint32_t addr) {
    asm volatile("ldmatrix.sync.aligned.m8n8.x4.shared.b16 {%0,%1,%2,%3}, [%4];\n"
                 : "=r"(r0), "=r"(r1), "=r"(r2), "=r"(r3) : "r"(addr));
}
__device__ __forceinline__ void ldmatrix_x2_trans(uint32_t& r0, uint32_t& r1, uint32_t addr) {
    asm volatile("ldmatrix.sync.aligned.m8n8.x2.trans.shared.b16 {%0,%1}, [%2];\n"
                 : "=r"(r0), "=r"(r1) : "r"(addr));
}
__device__ __forceinline__ void mma_f16acc(uint32_t c[2], const uint32_t a[4], const uint32_t b[2]) {
    asm volatile("mma.sync.aligned.m16n8k16.row.col.f16.f16.f16.f16 "
                 "{%0,%1}, {%2,%3,%4,%5}, {%6,%7}, {%0,%1};\n"
                 : "+r"(c[0]), "+r"(c[1])
                 : "r"(a[0]), "r"(a[1]), "r"(a[2]), "r"(a[3]), "r"(b[0]), "r"(b[1]));
}
__device__ __forceinline__ void mma_f32acc(float c[4], const uint32_t a[4], const uint32_t b[2]) {
    asm volatile("mma.sync.aligned.m16n8k16.row.col.f32.f16.f16.f32 "
                 "{%0,%1,%2,%3}, {%4,%5,%6,%7}, {%8,%9}, {%0,%1,%2,%3};\n"
                 : "+f"(c[0]), "+f"(c[1]), "+f"(c[2]), "+f"(c[3])
                 : "r"(a[0]), "r"(a[1]), "r"(a[2]), "r"(a[3]), "r"(b[0]), "r"(b[1]));
}
__device__ __forceinline__ float gelu_f(float v) {
    return 0.5f * v * (1.0f + erff(v * 0.7071067811865476f));
}
__device__ __forceinline__ int orig_to_win(int t) {
    int b = t >> 12, rem = t & 4095;
    int r = rem >> 6, c = rem & 63;
    int wi = (b << 6) + ((r >> 3) << 3) + (c >> 3);
    return (wi << 6) + ((r & 7) << 3) + (c & 7);
}
__device__ __forceinline__ int win_to_orig(int tw) {
    int wi = tw >> 6, k = tw & 63;
    int b = wi >> 6, w64 = wi & 63;
    int r = ((w64 >> 3) << 3) + (k >> 3);
    int c = ((w64 & 7) << 3) + (k & 7);
    return (b << 12) + (r << 6) + c;
}
__device__ __forceinline__ size_t swz_off(int row, int k, int Kd) {
    return ((size_t)((row >> 7) * (Kd >> 6) + (k >> 6)) << 14)
         + (size_t)((row & 127) * 128 + ((((k & 63) >> 3) ^ (row & 7)) << 4) + (k & 7) * 2);
}

// ---------------- fused weight convert -> swizzled fp16 tiles ----------------
__global__ void cvt_all_kernel(const float* __restrict__ wqkv, const float* __restrict__ wproj,
                               const float* __restrict__ wfc1, const float* __restrict__ wfc2,
                               __half* __restrict__ out) {
    int i = blockIdx.x * blockDim.x + threadIdx.x;
    int li = i * 8;
    const float* src; size_t basebyte; int Kd; int loc;
    if (li < WOFF_PROJ)      { src = wqkv;  loc = li;             basebyte = 0;                    Kd = 256; }
    else if (li < WOFF_FC1)  { src = wproj; loc = li - WOFF_PROJ; basebyte = (size_t)WOFF_PROJ*2;  Kd = 256; }
    else if (li < WOFF_FC2)  { src = wfc1;  loc = li - WOFF_FC1;  basebyte = (size_t)WOFF_FC1*2;   Kd = 256; }
    else                     { src = wfc2;  loc = li - WOFF_FC2;  basebyte = (size_t)WOFF_FC2*2;   Kd = 1024; }
    float4 a = *(const float4*)(src + loc);
    float4 b = *(const float4*)(src + loc + 4);
    int row = loc / Kd, k = loc % Kd;
    size_t off = basebyte + swz_off(row, k, Kd);
    __half2 p0 = __floats2half2_rn(a.x, a.y);
    __half2 p1 = __floats2half2_rn(a.z, a.w);
    __half2 p2 = __floats2half2_rn(b.x, b.y);
    __half2 p3 = __floats2half2_rn(b.z, b.w);
    uint4 pk;
    pk.x = *(uint32_t*)&p0; pk.y = *(uint32_t*)&p1; pk.z = *(uint32_t*)&p2; pk.w = *(uint32_t*)&p3;
    *(uint4*)((char*)out + off) = pk;
}

// ---------------- bias table precompute: g_bias[h][n][m] ----------------
__global__ void bias_kernel(const float* __restrict__ btab, float* __restrict__ bout) {
    int t = blockIdx.x * blockDim.x + threadIdx.x;
    int m = t & 63, n = (t >> 6) & 63, h = t >> 12;
    int rel = ((n >> 3) - (m >> 3) + 7) * 15 + ((n & 7) - (m & 7) + 7);
    bout[t] = btab[rel * 8 + h];
}

// ---------------- LayerNorm (warp per token), optional window-permute ----------------
template<int PERM>
__global__ __launch_bounds__(256) void ln_kernel(const float* __restrict__ x,
                                                 const float* __restrict__ g,
                                                 const float* __restrict__ b,
                                                 __half* __restrict__ out) {
    int warp = (blockIdx.x * 256 + threadIdx.x) >> 5;
    int lane = threadIdx.x & 31;
    const float* row = x + (size_t)warp * DIMC + lane * 8;
    float4 v0 = *(const float4*)row;
    float4 v1 = *(const float4*)(row + 4);
    float s = (v0.x + v0.y) + (v0.z + v0.w) + ((v1.x + v1.y) + (v1.z + v1.w));
#pragma unroll
    for (int o = 16; o; o >>= 1) s += __shfl_xor_sync(0xffffffffu, s, o);
    float mu = s * (1.0f / 256.0f);
    float d[8] = { v0.x - mu, v0.y - mu, v0.z - mu, v0.w - mu,
                   v1.x - mu, v1.y - mu, v1.z - mu, v1.w - mu };
    float ss = 0.f;
#pragma unroll
    for (int i = 0; i < 8; i++) ss += d[i] * d[i];
#pragma unroll
    for (int o = 16; o; o >>= 1) ss += __shfl_xor_sync(0xffffffffu, ss, o);
    float rstd = rsqrtf(ss * (1.0f / 256.0f) + 1e-5f);
    float4 gg0 = *(const float4*)(g + lane * 8);
    float4 gg1 = *(const float4*)(g + lane * 8 + 4);
    float4 bb0 = *(const float4*)(b + lane * 8);
    float4 bb1 = *(const float4*)(b + lane * 8 + 4);
    float y[8];
    y[0] = d[0] * rstd * gg0.x + bb0.x;  y[1] = d[1] * rstd * gg0.y + bb0.y;
    y[2] = d[2] * rstd * gg0.z + bb0.z;  y[3] = d[3] * rstd * gg0.w + bb0.w;
    y[4] = d[4] * rstd * gg1.x + bb1.x;  y[5] = d[5] * rstd * gg1.y + bb1.y;
    y[6] = d[6] * rstd * gg1.z + bb1.z;  y[7] = d[7] * rstd * gg1.w + bb1.w;
    int orow = PERM ? orig_to_win(warp) : warp;
    __half2 p0 = __floats2half2_rn(y[0], y[1]);
    __half2 p1 = __floats2half2_rn(y[2], y[3]);
    __half2 p2 = __floats2half2_rn(y[4], y[5]);
    __half2 p3 = __floats2half2_rn(y[6], y[7]);
    uint4 pk;
    pk.x = *(uint32_t*)&p0; pk.y = *(uint32_t*)&p1; pk.z = *(uint32_t*)&p2; pk.w = *(uint32_t*)&p3;
    *(uint4*)((char*)out + swz_off(orow, lane * 8, 256)) = pk;
}

// ---------------- fp16 TN GEMM (f16 accumulate), bulk tile loads ----------------
// Tile 128x128, 8 warps (4M x 2N), warp tile 32x64, 3-stage ring, 2 CTAs/SM.
// GRID: x = N-blocks (fast-varying -> A-tile L2 reuse), y = M-blocks.
// EPI 0: qkv (+bias -> fp16 LINEAR out, stride 768)
// EPI 1: proj (+bias, +residual gather x[win_to_orig] -> fp32 x1 linear, window order)
// EPI 2: fc1 (+bias, GELU -> fp16 SWIZZLED out, K=1024 image)
// EPI 3: fc2 (+bias, +residual x1(win) -> fp32 out scattered to orig order)
#define STG 32768
#define GSMEM (3 * STG + 64)

template<int N, int K, int EPI>
__global__ __launch_bounds__(256, 2) void gemm_kernel(const __half* __restrict__ A,
                                                      const __half* __restrict__ Bw,
                                                      const float* __restrict__ bias,
                                                      const float* __restrict__ res,
                                                      float* __restrict__ outf,
                                                      __half* __restrict__ outb) {
    extern __shared__ __align__(128) uint8_t dynsm[];
    const int tid = threadIdx.x;
    const int lane = tid & 31;
    const int wid = tid >> 5;
    const int wm = wid & 3;
    const int wn = wid >> 2;
    const int m0 = blockIdx.y * 128;      // swapped: y = M
    const int n0 = blockIdx.x * 128;      // swapped: x = N (fast)
    const uint32_t sbase = smem_u32(dynsm);
    const uint32_t mb = sbase + 3 * STG;
    constexpr int KT = K / 64;

    if (tid == 0) { mbar_init(mb, 1); mbar_init(mb + 8, 1); mbar_init(mb + 16, 1); }
    __syncthreads();

    auto issue = [&](int kt) {
        uint32_t s = (uint32_t)(kt % 3);
        uint32_t mbs = mb + s * 8;
        mbar_expect_tx(mbs, 32768u);
        const char* srcA = (const char*)A + ((size_t)blockIdx.y * KT + kt) * 16384;
        const char* srcB = (const char*)Bw + ((size_t)blockIdx.x * KT + kt) * 16384;
        bulk_g2s(sbase + s * STG, srcA, 16384u, mbs);
        bulk_g2s(sbase + s * STG + 16384u, srcB, 16384u, mbs);
    };
    if (tid == 0) { issue(0); issue(1); }

    uint32_t acc[2][8][2];
#pragma unroll
    for (int a = 0; a < 2; a++)
#pragma unroll
        for (int bq = 0; bq < 8; bq++) { acc[a][bq][0] = 0u; acc[a][bq][1] = 0u; }

    const int ti = lane >> 3, rr = lane & 7;
#pragma unroll 1
    for (int kt = 0; kt < KT; kt++) {
        __syncthreads();
        if (tid == 0 && kt + 2 < KT) issue(kt + 2);
        mbar_wait(mb + (uint32_t)(kt % 3) * 8, (uint32_t)((kt / 3) & 1));
        uint32_t abase = sbase + (uint32_t)(kt % 3) * STG;
        uint32_t bbase = abase + 16384;
#pragma unroll
        for (int ks = 0; ks < 4; ks++) {
            int kcb = ks * 2;
            uint32_t afr[2][4];
#pragma unroll
            for (int mt = 0; mt < 2; mt++) {
                int row = wm * 32 + mt * 16 + ((ti & 1) ? 8 : 0) + rr;
                int kc = kcb + (ti >> 1);
                uint32_t addr = abase + ((((uint32_t)row << 3) | (uint32_t)(kc ^ (row & 7))) << 4);
                ldmatrix_x4(afr[mt][0], afr[mt][1], afr[mt][2], afr[mt][3], addr);
            }
            uint32_t bfr[8][2];
#pragma unroll
            for (int ng = 0; ng < 4; ng++) {
                int row = wn * 64 + ng * 16 + ((ti >> 1) ? 8 : 0) + rr;
                int kc = kcb + (ti & 1);
                uint32_t addr = bbase + ((((uint32_t)row << 3) | (uint32_t)(kc ^ (row & 7))) << 4);
                uint32_t r0, r1, r2, r3;
                ldmatrix_x4(r0, r1, r2, r3, addr);
                bfr[2 * ng][0] = r0;     bfr[2 * ng][1] = r1;
                bfr[2 * ng + 1][0] = r2; bfr[2 * ng + 1][1] = r3;
            }
#pragma unroll
            for (int mt = 0; mt < 2; mt++)
#pragma unroll
                for (int nt = 0; nt < 8; nt++)
                    mma_f16acc(acc[mt][nt], afr[mt], bfr[nt]);
        }
    }

    int lrow = lane >> 2, lc2 = (lane & 3) * 2;
#pragma unroll
    for (int mt = 0; mt < 2; mt++) {
#pragma unroll
        for (int hh = 0; hh < 2; hh++) {
            int r = m0 + wm * 32 + mt * 16 + lrow + hh * 8;
            if constexpr (EPI == 0) {
                __half* op = outb + (size_t)r * N;
#pragma unroll
                for (int nt = 0; nt < 8; nt++) {
                    int c = n0 + wn * 64 + nt * 8 + lc2;
                    float2 bb = *(const float2*)(bias + c);
                    float2 cv = __half22float2(*(__half2*)&acc[mt][nt][hh]);
                    *(__half2*)(op + c) = __floats2half2_rn(cv.x + bb.x, cv.y + bb.y);
                }
            } else if constexpr (EPI == 2) {
#pragma unroll
                for (int nt = 0; nt < 8; nt++) {
                    int c = n0 + wn * 64 + nt * 8 + lc2;
                    float2 bb = *(const float2*)(bias + c);
                    float2 cv = __half22float2(*(__half2*)&acc[mt][nt][hh]);
                    *(__half2*)((char*)outb + swz_off(r, c, 1024)) =
                        __floats2half2_rn(gelu_f(cv.x + bb.x), gelu_f(cv.y + bb.y));
                }
            } else if constexpr (EPI == 1) {
                int torig = win_to_orig(r);
                const float* xr = res + (size_t)torig * 256;
                float* op = outf + (size_t)r * 256;
#pragma unroll
                for (int nt = 0; nt < 8; nt++) {
                    int c = n0 + wn * 64 + nt * 8 + lc2;
                    float2 bb = *(const float2*)(bias + c);
                    float2 cv = __half22float2(*(__half2*)&acc[mt][nt][hh]);
                    float2 xres = *(const float2*)(xr + c);
                    *(float2*)(op + c) = make_float2(xres.x + cv.x + bb.x, xres.y + cv.y + bb.y);
                }
            } else {
                int torig = win_to_orig(r);
                const float* x1r = res + (size_t)r * 256;
                float* op = outf + (size_t)torig * 256;
#pragma unroll
                for (int nt = 0; nt < 8; nt++) {
                    int c = n0 + wn * 64 + nt * 8 + lc2;
                    float2 bb = *(const float2*)(bias + c);
                    float2 cv = __half22float2(*(__half2*)&acc[mt][nt][hh]);
                    float2 rr2 = *(const float2*)(x1r + c);
                    *(float2*)(op + c) = make_float2(rr2.x + cv.x + bb.x, rr2.y + cv.y + bb.y);
                }
            }
        }
    }
}

// ---------------- windowed attention: fp16 in, f32 accum; swizzled fp16 out ----------------
#define ATT_PITCH 1552
#define ATT_SMEM (64 * ATT_PITCH)

__global__ __launch_bounds__(256, 2) void attn_kernel(const __half* __restrict__ qkv,
                                                      const float* __restrict__ bias_pre,
                                                      __half* __restrict__ out) {
    extern __shared__ __align__(128) uint8_t dynsm[];
    const int w = blockIdx.x;
    const int tid = threadIdx.x;
    const int h = tid >> 5, lane = tid & 31;
    const uint32_t sb = smem_u32(dynsm);
    const __half* gw = qkv + (size_t)w * 49152;

#pragma unroll
    for (int i = 0; i < 24; i++) {
        int ch = tid + i * 256;
        int r = ch / 96, c = ch % 96;
        cp_async16(sb + (uint32_t)(r * ATT_PITCH + c * 16), gw + r * 768 + c * 8);
    }
    cp_commit();
    asm volatile("cp.async.wait_group 0;\n" ::: "memory");
    __syncthreads();

    const uint32_t qbase = sb + (uint32_t)(h * 32) * 2;
    const uint32_t kbase = sb + (uint32_t)(256 + h * 32) * 2;
    const uint32_t vbase = sb + (uint32_t)(512 + h * 32) * 2;
    const float* bp = bias_pre + h * 4096;
    const float scale = 0.17677669529663688f;
    const int ti = lane >> 3, rr = lane & 7;
    const int lq = lane >> 2, lc = (lane & 3) * 2;

#pragma unroll 1
    for (int i = 0; i < 4; i++) {
        uint32_t qf[2][4];
#pragma unroll
        for (int ks = 0; ks < 2; ks++) {
            int row = i * 16 + ((ti & 1) ? 8 : 0) + rr;
            uint32_t addr = qbase + (uint32_t)(row * ATT_PITCH) + (uint32_t)((ks * 2 + (ti >> 1)) * 16);
            ldmatrix_x4(qf[ks][0], qf[ks][1], qf[ks][2], qf[ks][3], addr);
        }
        float sacc[8][4];
#pragma unroll
        for (int j = 0; j < 8; j++)
#pragma unroll
            for (int c = 0; c < 4; c++) sacc[j][c] = 0.f;
#pragma unroll
        for (int ks = 0; ks < 2; ks++) {
#pragma unroll
            for (int ng = 0; ng < 4; ng++) {
                int row = ng * 16 + ((ti >> 1) ? 8 : 0) + rr;
                uint32_t addr = kbase + (uint32_t)(row * ATT_PITCH) + (uint32_t)((ks * 2 + (ti & 1)) * 16);
                uint32_t b0, b1, b2, b3;
                ldmatrix_x4(b0, b1, b2, b3, addr);
                uint32_t bf0[2] = { b0, b1 }, bf1[2] = { b2, b3 };
                mma_f32acc(sacc[2 * ng],     qf[ks], bf0);
                mma_f32acc(sacc[2 * ng + 1], qf[ks], bf1);
            }
        }
        int r0 = i * 16 + lq, r1 = r0 + 8;
        float p[8][4];
        float mx0 = -1e30f, mx1 = -1e30f;
#pragma unroll
        for (int j = 0; j < 8; j++) {
            float2 b0 = *(const float2*)(bp + r0 * 64 + j * 8 + lc);
            float2 b1 = *(const float2*)(bp + r1 * 64 + j * 8 + lc);
            p[j][0] = fmaf(sacc[j][0], scale, b0.x);
            p[j][1] = fmaf(sacc[j][1], scale, b0.y);
            p[j][2] = fmaf(sacc[j][2], scale, b1.x);
            p[j][3] = fmaf(sacc[j][3], scale, b1.y);
            mx0 = fmaxf(mx0, fmaxf(p[j][0], p[j][1]));
            mx1 = fmaxf(mx1, fmaxf(p[j][2], p[j][3]));
        }
        mx0 = fmaxf(mx0, __shfl_xor_sync(0xffffffffu, mx0, 1));
        mx0 = fmaxf(mx0, __shfl_xor_sync(0xffffffffu, mx0, 2));
        mx1 = fmaxf(mx1, __shfl_xor_sync(0xffffffffu, mx1, 1));
        mx1 = fmaxf(mx1, __shfl_xor_sync(0xffffffffu, mx1, 2));
        float sm0 = 0.f, sm1 = 0.f;
#pragma unroll
        for (int j = 0; j < 8; j++) {
            p[j][0] = __expf(p[j][0] - mx0);
            p[j][1] = __expf(p[j][1] - mx0);
            p[j][2] = __expf(p[j][2] - mx1);
            p[j][3] = __expf(p[j][3] - mx1);
            sm0 += p[j][0] + p[j][1];
            sm1 += p[j][2] + p[j][3];
        }
        sm0 += __shfl_xor_sync(0xffffffffu, sm0, 1);
        sm0 += __shfl_xor_sync(0xffffffffu, sm0, 2);
        sm1 += __shfl_xor_sync(0xffffffffu, sm1, 1);
        sm1 += __shfl_xor_sync(0xffffffffu, sm1, 2);
        float inv0 = 1.0f / sm0, inv1 = 1.0f / sm1;

        uint32_t ap[4][4];
#pragma unroll
        for (int ks = 0; ks < 4; ks++) {
            __half2 t0 = __floats2half2_rn(p[2 * ks][0],     p[2 * ks][1]);
            __half2 t1 = __floats2half2_rn(p[2 * ks][2],     p[2 * ks][3]);
            __half2 t2 = __floats2half2_rn(p[2 * ks + 1][0], p[2 * ks + 1][1]);
            __half2 t3 = __floats2half2_rn(p[2 * ks + 1][2], p[2 * ks + 1][3]);
            ap[ks][0] = *(uint32_t*)&t0; ap[ks][1] = *(uint32_t*)&t1;
            ap[ks][2] = *(uint32_t*)&t2; ap[ks][3] = *(uint32_t*)&t3;
        }
        float o[4][4];
#pragma unroll
        for (int jj = 0; jj < 4; jj++)
#pragma unroll
            for (int c = 0; c < 4; c++) o[jj][c] = 0.f;
#pragma unroll
        for (int ks = 0; ks < 4; ks++) {
#pragma unroll
            for (int jj = 0; jj < 4; jj++) {
                uint32_t bv[2];
                uint32_t addr = vbase + (uint32_t)((ks * 16 + (lane & 15)) * ATT_PITCH) + (uint32_t)(jj * 16);
                ldmatrix_x2_trans(bv[0], bv[1], addr);
                mma_f32acc(o[jj], ap[ks], bv);
            }
        }
        int row0 = w * 64 + r0, row1 = w * 64 + r1;
#pragma unroll
        for (int jj = 0; jj < 4; jj++) {
            int k = h * 32 + jj * 8 + lc;
            *(__half2*)((char*)out + swz_off(row0, k, 256)) =
                __floats2half2_rn(o[jj][0] * inv0, o[jj][1] * inv0);
            *(__half2*)((char*)out + swz_off(row1, k, 256)) =
                __floats2half2_rn(o[jj][2] * inv1, o[jj][3] * inv1);
        }
    }
}

// ---------------- launch ----------------
extern "C" void kernel_launch(void* const* d_in, const int* in_sizes, int n_in,
                              void* d_out, int out_size) {
    const float* x      = (const float*)d_in[0];
    const float* g1     = (const float*)d_in[2];
    const float* b1     = (const float*)d_in[3];
    const float* w_qkv  = (const float*)d_in[4];
    const float* b_qkv  = (const float*)d_in[5];
    const float* btab   = (const float*)d_in[6];
    const float* w_proj = (const float*)d_in[7];
    const float* b_proj = (const float*)d_in[8];
    const float* g2     = (const float*)d_in[9];
    const float* b2     = (const float*)d_in[10];
    const float* w_fc1  = (const float*)d_in[11];
    const float* b_fc1  = (const float*)d_in[12];
    const float* w_fc2  = (const float*)d_in[13];
    const float* b_fc2  = (const float*)d_in[14];
    float* out = (float*)d_out;

    __half *xw, *qkv, *attn, *xn2, *hbuf, *wall;
    float *x1, *bpre;
    cudaGetSymbolAddress((void**)&xw,   g_xw);
    cudaGetSymbolAddress((void**)&qkv,  g_qkv);
    cudaGetSymbolAddress((void**)&attn, g_attn);
    cudaGetSymbolAddress((void**)&x1,   g_x1);
    cudaGetSymbolAddress((void**)&xn2,  g_xn2);
    cudaGetSymbolAddress((void**)&hbuf, g_h);
    cudaGetSymbolAddress((void**)&wall, g_wall);
    cudaGetSymbolAddress((void**)&bpre, g_bias);

    __half* wq = wall + WOFF_QKV;
    __half* wp = wall + WOFF_PROJ;
    __half* w1 = wall + WOFF_FC1;
    __half* w2 = wall + WOFF_FC2;

    cudaFuncSetAttribute(gemm_kernel<768, 256, 0>,  cudaFuncAttributeMaxDynamicSharedMemorySize, GSMEM);
    cudaFuncSetAttribute(gemm_kernel<256, 256, 1>,  cudaFuncAttributeMaxDynamicSharedMemorySize, GSMEM);
    cudaFuncSetAttribute(gemm_kernel<1024, 256, 2>, cudaFuncAttributeMaxDynamicSharedMemorySize, GSMEM);
    cudaFuncSetAttribute(gemm_kernel<256, 1024, 3>, cudaFuncAttributeMaxDynamicSharedMemorySize, GSMEM);
    cudaFuncSetAttribute(attn_kernel, cudaFuncAttributeMaxDynamicSharedMemorySize, ATT_SMEM);

    cvt_all_kernel<<<WTOT / 8 / 256, 256>>>(w_qkv, w_proj, w_fc1, w_fc2, wall);
    bias_kernel<<<HEADS * 64 * 64 / 256, 256>>>(btab, bpre);
    ln_kernel<1><<<TTOK / 8, 256>>>(x, g1, b1, xw);
    gemm_kernel<768, 256, 0><<<dim3(6, TTOK / 128), 256, GSMEM>>>(
        xw, wq, b_qkv, nullptr, nullptr, qkv);
    attn_kernel<<<2048, 256, ATT_SMEM>>>(qkv, bpre, attn);
    gemm_kernel<256, 256, 1><<<dim3(2, TTOK / 128), 256, GSMEM>>>(
        attn, wp, b_proj, x, x1, nullptr);
    ln_kernel<0><<<TTOK / 8, 256>>>(x1, g2, b2, xn2);
    gemm_kernel<1024, 256, 2><<<dim3(8, TTOK / 128), 256, GSMEM>>>(
        xn2, w1, b_fc1, nullptr, nullptr, hbuf);
    gemm_kernel<256, 1024, 3><<<dim3(2, TTOK / 128), 256, GSMEM>>>(
        hbuf, w2, b_fc2, x1, out, nullptr);
}

// round 14
// speedup vs baseline: 1.1290x; 1.0198x over previous
#include <cuda_runtime.h>
#include <cuda_fp16.h>
#include <math.h>
#include <stdint.h>

#define DIMC 256
#define HEADS 8
#define TTOK 131072          // 32*4096 tokens
#define HIDD 1024

// ---------------- scratch (static __device__, no allocs) ----------------
// Swizzled 16KB tile images: tile = (row>>7)*(K/64) + (k>>6);
// byte = (row&127)*128 + ((((k&63)>>3) ^ (row&7))<<4) + (k&7)*2
__device__ __align__(128) __half g_xw  [(size_t)TTOK * DIMC];     // swizzled, K=256
__device__ __align__(128) __half g_qkv [(size_t)TTOK * 3 * DIMC]; // LINEAR (attn input)
__device__ __align__(128) __half g_attn[(size_t)TTOK * DIMC];     // swizzled, K=256
__device__ __align__(128) __half g_x1  [(size_t)TTOK * DIMC];     // linear fp16, window order
__device__ __align__(128) __half g_xn2 [(size_t)TTOK * DIMC];     // swizzled, K=256
__device__ __align__(128) __half g_h   [(size_t)TTOK * HIDD];     // swizzled, K=1024
__device__ __align__(128) __half g_wall[(3 * DIMC + DIMC + HIDD + DIMC) * DIMC + DIMC * HIDD];
__device__ float g_bias[HEADS * 64 * 64];

#define WOFF_QKV  0
#define WOFF_PROJ (3 * DIMC * DIMC)
#define WOFF_FC1  (WOFF_PROJ + DIMC * DIMC)
#define WOFF_FC2  (WOFF_FC1 + HIDD * DIMC)
#define WTOT      (WOFF_FC2 + DIMC * HIDD)

// ---------------- helpers ----------------
__device__ __forceinline__ uint32_t smem_u32(const void* p) {
    return (uint32_t)__cvta_generic_to_shared(p);
}
__device__ __forceinline__ void cp_async16(uint32_t saddr, const void* gptr) {
    asm volatile("cp.async.cg.shared.global [%0], [%1], 16;\n" :: "r"(saddr), "l"(gptr));
}
__device__ __forceinline__ void cp_commit() { asm volatile("cp.async.commit_group;\n"); }
__device__ __forceinline__ void bulk_g2s(uint32_t dst, const void* src, uint32_t bytes, uint32_t mbar) {
    asm volatile("cp.async.bulk.shared::cluster.global.mbarrier::complete_tx::bytes [%0], [%1], %2, [%3];"
                 :: "r"(dst), "l"(src), "r"(bytes), "r"(mbar) : "memory");
}
__device__ __forceinline__ void mbar_init(uint32_t mbar, uint32_t cnt) {
    asm volatile("mbarrier.init.shared.b64 [%0], %1;" :: "r"(mbar), "r"(cnt) : "memory");
}
__device__ __forceinline__ void mbar_expect_tx(uint32_t mbar, uint32_t bytes) {
    asm volatile("mbarrier.arrive.expect_tx.shared.b64 _, [%0], %1;" :: "r"(mbar), "r"(bytes) : "memory");
}
__device__ __forceinline__ void mbar_wait(uint32_t mbar, uint32_t parity) {
    asm volatile("{\n\t.reg .pred P1;\n\t"
                 "WAIT_%=:\n\t"
                 "mbarrier.try_wait.parity.acquire.cta.shared::cta.b64 P1, [%0], %1, 0x989680;\n\t"
                 "@P1 bra.uni DONE_%=;\n\t"
                 "bra.uni WAIT_%=;\n\t"
                 "DONE_%=:\n\t}"
                 :: "r"(mbar), "r"(parity) : "memory");
}
__device__ __forceinline__ void ldmatrix_x4(uint32_t& r0, uint32_t& r1, uint32_t& r2, uint32_t& r3, uint32_t addr) {
    asm volatile("ldmatrix.sync.aligned.m8n8.x4.shared.b16 {%0,%1,%2,%3}, [%4];\n"
                 : "=r"(r0), "=r"(r1), "=r"(r2), "=r"(r3) : "r"(addr));
}
__device__ __forceinline__ void ldmatrix_x2_trans(uint32_t& r0, uint32_t& r1, uint32_t addr) {
    asm volatile("ldmatrix.sync.aligned.m8n8.x2.trans.shared.b16 {%0,%1}, [%2];\n"
                 : "=r"(r0), "=r"(r1) : "r"(addr));
}
__device__ __forceinline__ void mma_f16acc(uint32_t c[2], const uint32_t a[4], const uint32_t b[2]) {
    asm volatile("mma.sync.aligned.m16n8k16.row.col.f16.f16.f16.f16 "
                 "{%0,%1}, {%2,%3,%4,%5}, {%6,%7}, {%0,%1};\n"
                 : "+r"(c[0]), "+r"(c[1])
                 : "r"(a[0]), "r"(a[1]), "r"(a[2]), "r"(a[3]), "r"(b[0]), "r"(b[1]));
}
__device__ __forceinline__ void mma_f32acc(float c[4], const uint32_t a[4], const uint32_t b[2]) {
    asm volatile("mma.sync.aligned.m16n8k16.row.col.f32.f16.f16.f32 "
                 "{%0,%1,%2,%3}, {%4,%5,%6,%7}, {%8,%9}, {%0,%1,%2,%3};\n"
                 : "+f"(c[0]), "+f"(c[1]), "+f"(c[2]), "+f"(c[3])
                 : "r"(a[0]), "r"(a[1]), "r"(a[2]), "r"(a[3]), "r"(b[0]), "r"(b[1]));
}
__device__ __forceinline__ float gelu_f(float v) {
    return 0.5f * v * (1.0f + erff(v * 0.7071067811865476f));
}
__device__ __forceinline__ int orig_to_win(int t) {
    int b = t >> 12, rem = t & 4095;
    int r = rem >> 6, c = rem & 63;
    int wi = (b << 6) + ((r >> 3) << 3) + (c >> 3);
    return (wi << 6) + ((r & 7) << 3) + (c & 7);
}
__device__ __forceinline__ int win_to_orig(int tw) {
    int wi = tw >> 6, k = tw & 63;
    int b = wi >> 6, w64 = wi & 63;
    int r = ((w64 >> 3) << 3) + (k >> 3);
    int c = ((w64 & 7) << 3) + (k & 7);
    return (b << 12) + (r << 6) + c;
}
__device__ __forceinline__ size_t swz_off(int row, int k, int Kd) {
    return ((size_t)((row >> 7) * (Kd >> 6) + (k >> 6)) << 14)
         + (size_t)((row & 127) * 128 + ((((k & 63) >> 3) ^ (row & 7)) << 4) + (k & 7) * 2);
}

// ---------------- fused weight convert -> swizzled fp16 tiles ----------------
__global__ void cvt_all_kernel(const float* __restrict__ wqkv, const float* __restrict__ wproj,
                               const float* __restrict__ wfc1, const float* __restrict__ wfc2,
                               __half* __restrict__ out) {
    int i = blockIdx.x * blockDim.x + threadIdx.x;
    int li = i * 8;
    const float* src; size_t basebyte; int Kd; int loc;
    if (li < WOFF_PROJ)      { src = wqkv;  loc = li;             basebyte = 0;                    Kd = 256; }
    else if (li < WOFF_FC1)  { src = wproj; loc = li - WOFF_PROJ; basebyte = (size_t)WOFF_PROJ*2;  Kd = 256; }
    else if (li < WOFF_FC2)  { src = wfc1;  loc = li - WOFF_FC1;  basebyte = (size_t)WOFF_FC1*2;   Kd = 256; }
    else                     { src = wfc2;  loc = li - WOFF_FC2;  basebyte = (size_t)WOFF_FC2*2;   Kd = 1024; }
    float4 a = *(const float4*)(src + loc);
    float4 b = *(const float4*)(src + loc + 4);
    int row = loc / Kd, k = loc % Kd;
    size_t off = basebyte + swz_off(row, k, Kd);
    __half2 p0 = __floats2half2_rn(a.x, a.y);
    __half2 p1 = __floats2half2_rn(a.z, a.w);
    __half2 p2 = __floats2half2_rn(b.x, b.y);
    __half2 p3 = __floats2half2_rn(b.z, b.w);
    uint4 pk;
    pk.x = *(uint32_t*)&p0; pk.y = *(uint32_t*)&p1; pk.z = *(uint32_t*)&p2; pk.w = *(uint32_t*)&p3;
    *(uint4*)((char*)out + off) = pk;
}

// ---------------- bias table precompute: g_bias[h][n][m] ----------------
__global__ void bias_kernel(const float* __restrict__ btab, float* __restrict__ bout) {
    int t = blockIdx.x * blockDim.x + threadIdx.x;
    int m = t & 63, n = (t >> 6) & 63, h = t >> 12;
    int rel = ((n >> 3) - (m >> 3) + 7) * 15 + ((n & 7) - (m & 7) + 7);
    bout[t] = btab[rel * 8 + h];
}

// ---------------- LayerNorm (warp per token), templated input, optional permute ----------------
template<typename TIN, int PERM>
__global__ __launch_bounds__(256) void ln_kernel(const TIN* __restrict__ x,
                                                 const float* __restrict__ g,
                                                 const float* __restrict__ b,
                                                 __half* __restrict__ out) {
    int warp = (blockIdx.x * 256 + threadIdx.x) >> 5;
    int lane = threadIdx.x & 31;
    float v[8];
    if constexpr (sizeof(TIN) == 4) {
        const float* row = (const float*)x + (size_t)warp * DIMC + lane * 8;
        float4 v0 = *(const float4*)row;
        float4 v1 = *(const float4*)(row + 4);
        v[0] = v0.x; v[1] = v0.y; v[2] = v0.z; v[3] = v0.w;
        v[4] = v1.x; v[5] = v1.y; v[6] = v1.z; v[7] = v1.w;
    } else {
        const __half* row = (const __half*)x + (size_t)warp * DIMC + lane * 8;
        uint4 pk = *(const uint4*)row;
        float2 f0 = __half22float2(*(__half2*)&pk.x);
        float2 f1 = __half22float2(*(__half2*)&pk.y);
        float2 f2 = __half22float2(*(__half2*)&pk.z);
        float2 f3 = __half22float2(*(__half2*)&pk.w);
        v[0] = f0.x; v[1] = f0.y; v[2] = f1.x; v[3] = f1.y;
        v[4] = f2.x; v[5] = f2.y; v[6] = f3.x; v[7] = f3.y;
    }
    float s = (v[0] + v[1]) + (v[2] + v[3]) + ((v[4] + v[5]) + (v[6] + v[7]));
#pragma unroll
    for (int o = 16; o; o >>= 1) s += __shfl_xor_sync(0xffffffffu, s, o);
    float mu = s * (1.0f / 256.0f);
    float d[8];
#pragma unroll
    for (int i = 0; i < 8; i++) d[i] = v[i] - mu;
    float ss = 0.f;
#pragma unroll
    for (int i = 0; i < 8; i++) ss += d[i] * d[i];
#pragma unroll
    for (int o = 16; o; o >>= 1) ss += __shfl_xor_sync(0xffffffffu, ss, o);
    float rstd = rsqrtf(ss * (1.0f / 256.0f) + 1e-5f);
    float4 gg0 = *(const float4*)(g + lane * 8);
    float4 gg1 = *(const float4*)(g + lane * 8 + 4);
    float4 bb0 = *(const float4*)(b + lane * 8);
    float4 bb1 = *(const float4*)(b + lane * 8 + 4);
    float y[8];
    y[0] = d[0] * rstd * gg0.x + bb0.x;  y[1] = d[1] * rstd * gg0.y + bb0.y;
    y[2] = d[2] * rstd * gg0.z + bb0.z;  y[3] = d[3] * rstd * gg0.w + bb0.w;
    y[4] = d[4] * rstd * gg1.x + bb1.x;  y[5] = d[5] * rstd * gg1.y + bb1.y;
    y[6] = d[6] * rstd * gg1.z + bb1.z;  y[7] = d[7] * rstd * gg1.w + bb1.w;
    int orow = PERM ? orig_to_win(warp) : warp;
    __half2 p0 = __floats2half2_rn(y[0], y[1]);
    __half2 p1 = __floats2half2_rn(y[2], y[3]);
    __half2 p2 = __floats2half2_rn(y[4], y[5]);
    __half2 p3 = __floats2half2_rn(y[6], y[7]);
    uint4 pk;
    pk.x = *(uint32_t*)&p0; pk.y = *(uint32_t*)&p1; pk.z = *(uint32_t*)&p2; pk.w = *(uint32_t*)&p3;
    *(uint4*)((char*)out + swz_off(orow, lane * 8, 256)) = pk;
}

// ---------------- fp16 TN GEMM (f16 accumulate), bulk tile loads ----------------
// Tile 128x128, 8 warps (4M x 2N), warp tile 32x64, 3-stage ring, 2 CTAs/SM.
// GRID: x = N-blocks (fast-varying -> A-tile L2 reuse), y = M-blocks.
// EPI 0: qkv (+bias -> fp16 LINEAR out, stride 768)
// EPI 1: proj (+bias, +residual gather x[win_to_orig] fp32 -> fp16 x1 linear, window order)
// EPI 2: fc1 (+bias, GELU -> fp16 SWIZZLED out, K=1024 image)
// EPI 3: fc2 (+bias, +residual x1(win, fp16) -> fp32 out scattered to orig order)
#define STG 32768
#define GSMEM (3 * STG + 64)

template<int N, int K, int EPI>
__global__ __launch_bounds__(256, 2) void gemm_kernel(const __half* __restrict__ A,
                                                      const __half* __restrict__ Bw,
                                                      const float* __restrict__ bias,
                                                      const float* __restrict__ resf,
                                                      const __half* __restrict__ res16,
                                                      float* __restrict__ outf,
                                                      __half* __restrict__ outb) {
    extern __shared__ __align__(128) uint8_t dynsm[];
    const int tid = threadIdx.x;
    const int lane = tid & 31;
    const int wid = tid >> 5;
    const int wm = wid & 3;
    const int wn = wid >> 2;
    const int m0 = blockIdx.y * 128;      // y = M
    const int n0 = blockIdx.x * 128;      // x = N (fast)
    const uint32_t sbase = smem_u32(dynsm);
    const uint32_t mb = sbase + 3 * STG;
    constexpr int KT = K / 64;

    if (tid == 0) { mbar_init(mb, 1); mbar_init(mb + 8, 1); mbar_init(mb + 16, 1); }
    __syncthreads();

    auto issue = [&](int kt) {
        uint32_t s = (uint32_t)(kt % 3);
        uint32_t mbs = mb + s * 8;
        mbar_expect_tx(mbs, 32768u);
        const char* srcA = (const char*)A + ((size_t)blockIdx.y * KT + kt) * 16384;
        const char* srcB = (const char*)Bw + ((size_t)blockIdx.x * KT + kt) * 16384;
        bulk_g2s(sbase + s * STG, srcA, 16384u, mbs);
        bulk_g2s(sbase + s * STG + 16384u, srcB, 16384u, mbs);
    };
    if (tid == 0) { issue(0); issue(1); }

    uint32_t acc[2][8][2];
#pragma unroll
    for (int a = 0; a < 2; a++)
#pragma unroll
        for (int bq = 0; bq < 8; bq++) { acc[a][bq][0] = 0u; acc[a][bq][1] = 0u; }

    const int ti = lane >> 3, rr = lane & 7;
#pragma unroll 1
    for (int kt = 0; kt < KT; kt++) {
        __syncthreads();
        if (tid == 0 && kt + 2 < KT) issue(kt + 2);
        mbar_wait(mb + (uint32_t)(kt % 3) * 8, (uint32_t)((kt / 3) & 1));
        uint32_t abase = sbase + (uint32_t)(kt % 3) * STG;
        uint32_t bbase = abase + 16384;
#pragma unroll
        for (int ks = 0; ks < 4; ks++) {
            int kcb = ks * 2;
            uint32_t afr[2][4];
#pragma unroll
            for (int mt = 0; mt < 2; mt++) {
                int row = wm * 32 + mt * 16 + ((ti & 1) ? 8 : 0) + rr;
                int kc = kcb + (ti >> 1);
                uint32_t addr = abase + ((((uint32_t)row << 3) | (uint32_t)(kc ^ (row & 7))) << 4);
                ldmatrix_x4(afr[mt][0], afr[mt][1], afr[mt][2], afr[mt][3], addr);
            }
            uint32_t bfr[8][2];
#pragma unroll
            for (int ng = 0; ng < 4; ng++) {
                int row = wn * 64 + ng * 16 + ((ti >> 1) ? 8 : 0) + rr;
                int kc = kcb + (ti & 1);
                uint32_t addr = bbase + ((((uint32_t)row << 3) | (uint32_t)(kc ^ (row & 7))) << 4);
                uint32_t r0, r1, r2, r3;
                ldmatrix_x4(r0, r1, r2, r3, addr);
                bfr[2 * ng][0] = r0;     bfr[2 * ng][1] = r1;
                bfr[2 * ng + 1][0] = r2; bfr[2 * ng + 1][1] = r3;
            }
#pragma unroll
            for (int mt = 0; mt < 2; mt++)
#pragma unroll
                for (int nt = 0; nt < 8; nt++)
                    mma_f16acc(acc[mt][nt], afr[mt], bfr[nt]);
        }
    }

    int lrow = lane >> 2, lc2 = (lane & 3) * 2;
#pragma unroll
    for (int mt = 0; mt < 2; mt++) {
#pragma unroll
        for (int hh = 0; hh < 2; hh++) {
            int r = m0 + wm * 32 + mt * 16 + lrow + hh * 8;
            if constexpr (EPI == 0) {
                __half* op = outb + (size_t)r * N;
#pragma unroll
                for (int nt = 0; nt < 8; nt++) {
                    int c = n0 + wn * 64 + nt * 8 + lc2;
                    float2 bb = *(const float2*)(bias + c);
                    float2 cv = __half22float2(*(__half2*)&acc[mt][nt][hh]);
                    *(__half2*)(op + c) = __floats2half2_rn(cv.x + bb.x, cv.y + bb.y);
                }
            } else if constexpr (EPI == 2) {
#pragma unroll
                for (int nt = 0; nt < 8; nt++) {
                    int c = n0 + wn * 64 + nt * 8 + lc2;
                    float2 bb = *(const float2*)(bias + c);
                    float2 cv = __half22float2(*(__half2*)&acc[mt][nt][hh]);
                    *(__half2*)((char*)outb + swz_off(r, c, 1024)) =
                        __floats2half2_rn(gelu_f(cv.x + bb.x), gelu_f(cv.y + bb.y));
                }
            } else if constexpr (EPI == 1) {
                // proj: x1(win, fp16) = x[orig](fp32) + acc + bias
                int torig = win_to_orig(r);
                const float* xr = resf + (size_t)torig * 256;
                __half* op = outb + (size_t)r * 256;
#pragma unroll
                for (int nt = 0; nt < 8; nt++) {
                    int c = n0 + wn * 64 + nt * 8 + lc2;
                    float2 bb = *(const float2*)(bias + c);
                    float2 cv = __half22float2(*(__half2*)&acc[mt][nt][hh]);
                    float2 xres = *(const float2*)(xr + c);
                    *(__half2*)(op + c) = __floats2half2_rn(xres.x + cv.x + bb.x,
                                                            xres.y + cv.y + bb.y);
                }
            } else {
                // fc2: out[orig](fp32) = x1[win](fp16) + acc + bias
                int torig = win_to_orig(r);
                const __half* x1r = res16 + (size_t)r * 256;
                float* op = outf + (size_t)torig * 256;
#pragma unroll
                for (int nt = 0; nt < 8; nt++) {
                    int c = n0 + wn * 64 + nt * 8 + lc2;
                    float2 bb = *(const float2*)(bias + c);
                    float2 cv = __half22float2(*(__half2*)&acc[mt][nt][hh]);
                    float2 rr2 = __half22float2(*(const __half2*)(x1r + c));
                    *(float2*)(op + c) = make_float2(rr2.x + cv.x + bb.x, rr2.y + cv.y + bb.y);
                }
            }
        }
    }
}

// ---------------- windowed attention: fp16 in, f32 accum; swizzled fp16 out ----------------
#define ATT_PITCH 1552
#define ATT_SMEM (64 * ATT_PITCH)

__global__ __launch_bounds__(256, 2) void attn_kernel(const __half* __restrict__ qkv,
                                                      const float* __restrict__ bias_pre,
                                                      __half* __restrict__ out) {
    extern __shared__ __align__(128) uint8_t dynsm[];
    const int w = blockIdx.x;
    const int tid = threadIdx.x;
    const int h = tid >> 5, lane = tid & 31;
    const uint32_t sb = smem_u32(dynsm);
    const __half* gw = qkv + (size_t)w * 49152;

#pragma unroll
    for (int i = 0; i < 24; i++) {
        int ch = tid + i * 256;
        int r = ch / 96, c = ch % 96;
        cp_async16(sb + (uint32_t)(r * ATT_PITCH + c * 16), gw + r * 768 + c * 8);
    }
    cp_commit();
    asm volatile("cp.async.wait_group 0;\n" ::: "memory");
    __syncthreads();

    const uint32_t qbase = sb + (uint32_t)(h * 32) * 2;
    const uint32_t kbase = sb + (uint32_t)(256 + h * 32) * 2;
    const uint32_t vbase = sb + (uint32_t)(512 + h * 32) * 2;
    const float* bp = bias_pre + h * 4096;
    const float scale = 0.17677669529663688f;
    const int ti = lane >> 3, rr = lane & 7;
    const int lq = lane >> 2, lc = (lane & 3) * 2;

#pragma unroll 1
    for (int i = 0; i < 4; i++) {
        uint32_t qf[2][4];
#pragma unroll
        for (int ks = 0; ks < 2; ks++) {
            int row = i * 16 + ((ti & 1) ? 8 : 0) + rr;
            uint32_t addr = qbase + (uint32_t)(row * ATT_PITCH) + (uint32_t)((ks * 2 + (ti >> 1)) * 16);
            ldmatrix_x4(qf[ks][0], qf[ks][1], qf[ks][2], qf[ks][3], addr);
        }
        float sacc[8][4];
#pragma unroll
        for (int j = 0; j < 8; j++)
#pragma unroll
            for (int c = 0; c < 4; c++) sacc[j][c] = 0.f;
#pragma unroll
        for (int ks = 0; ks < 2; ks++) {
#pragma unroll
            for (int ng = 0; ng < 4; ng++) {
                int row = ng * 16 + ((ti >> 1) ? 8 : 0) + rr;
                uint32_t addr = kbase + (uint32_t)(row * ATT_PITCH) + (uint32_t)((ks * 2 + (ti & 1)) * 16);
                uint32_t b0, b1, b2, b3;
                ldmatrix_x4(b0, b1, b2, b3, addr);
                uint32_t bf0[2] = { b0, b1 }, bf1[2] = { b2, b3 };
                mma_f32acc(sacc[2 * ng],     qf[ks], bf0);
                mma_f32acc(sacc[2 * ng + 1], qf[ks], bf1);
            }
        }
        int r0 = i * 16 + lq, r1 = r0 + 8;
        float p[8][4];
        float mx0 = -1e30f, mx1 = -1e30f;
#pragma unroll
        for (int j = 0; j < 8; j++) {
            float2 b0 = *(const float2*)(bp + r0 * 64 + j * 8 + lc);
            float2 b1 = *(const float2*)(bp + r1 * 64 + j * 8 + lc);
            p[j][0] = fmaf(sacc[j][0], scale, b0.x);
            p[j][1] = fmaf(sacc[j][1], scale, b0.y);
            p[j][2] = fmaf(sacc[j][2], scale, b1.x);
            p[j][3] = fmaf(sacc[j][3], scale, b1.y);
            mx0 = fmaxf(mx0, fmaxf(p[j][0], p[j][1]));
            mx1 = fmaxf(mx1, fmaxf(p[j][2], p[j][3]));
        }
        mx0 = fmaxf(mx0, __shfl_xor_sync(0xffffffffu, mx0, 1));
        mx0 = fmaxf(mx0, __shfl_xor_sync(0xffffffffu, mx0, 2));
        mx1 = fmaxf(mx1, __shfl_xor_sync(0xffffffffu, mx1, 1));
        mx1 = fmaxf(mx1, __shfl_xor_sync(0xffffffffu, mx1, 2));
        float sm0 = 0.f, sm1 = 0.f;
#pragma unroll
        for (int j = 0; j < 8; j++) {
            p[j][0] = __expf(p[j][0] - mx0);
            p[j][1] = __expf(p[j][1] - mx0);
            p[j][2] = __expf(p[j][2] - mx1);
            p[j][3] = __expf(p[j][3] - mx1);
            sm0 += p[j][0] + p[j][1];
            sm1 += p[j][2] + p[j][3];
        }
        sm0 += __shfl_xor_sync(0xffffffffu, sm0, 1);
        sm0 += __shfl_xor_sync(0xffffffffu, sm0, 2);
        sm1 += __shfl_xor_sync(0xffffffffu, sm1, 1);
        sm1 += __shfl_xor_sync(0xffffffffu, sm1, 2);
        float inv0 = 1.0f / sm0, inv1 = 1.0f / sm1;

        uint32_t ap[4][4];
#pragma unroll
        for (int ks = 0; ks < 4; ks++) {
            __half2 t0 = __floats2half2_rn(p[2 * ks][0],     p[2 * ks][1]);
            __half2 t1 = __floats2half2_rn(p[2 * ks][2],     p[2 * ks][3]);
            __half2 t2 = __floats2half2_rn(p[2 * ks + 1][0], p[2 * ks + 1][1]);
            __half2 t3 = __floats2half2_rn(p[2 * ks + 1][2], p[2 * ks + 1][3]);
            ap[ks][0] = *(uint32_t*)&t0; ap[ks][1] = *(uint32_t*)&t1;
            ap[ks][2] = *(uint32_t*)&t2; ap[ks][3] = *(uint32_t*)&t3;
        }
        float o[4][4];
#pragma unroll
        for (int jj = 0; jj < 4; jj++)
#pragma unroll
            for (int c = 0; c < 4; c++) o[jj][c] = 0.f;
#pragma unroll
        for (int ks = 0; ks < 4; ks++) {
#pragma unroll
            for (int jj = 0; jj < 4; jj++) {
                uint32_t bv[2];
                uint32_t addr = vbase + (uint32_t)((ks * 16 + (lane & 15)) * ATT_PITCH) + (uint32_t)(jj * 16);
                ldmatrix_x2_trans(bv[0], bv[1], addr);
                mma_f32acc(o[jj], ap[ks], bv);
            }
        }
        int row0 = w * 64 + r0, row1 = w * 64 + r1;
#pragma unroll
        for (int jj = 0; jj < 4; jj++) {
            int k = h * 32 + jj * 8 + lc;
            *(__half2*)((char*)out + swz_off(row0, k, 256)) =
                __floats2half2_rn(o[jj][0] * inv0, o[jj][1] * inv0);
            *(__half2*)((char*)out + swz_off(row1, k, 256)) =
                __floats2half2_rn(o[jj][2] * inv1, o[jj][3] * inv1);
        }
    }
}

// ---------------- launch ----------------
extern "C" void kernel_launch(void* const* d_in, const int* in_sizes, int n_in,
                              void* d_out, int out_size) {
    const float* x      = (const float*)d_in[0];
    const float* g1     = (const float*)d_in[2];
    const float* b1     = (const float*)d_in[3];
    const float* w_qkv  = (const float*)d_in[4];
    const float* b_qkv  = (const float*)d_in[5];
    const float* btab   = (const float*)d_in[6];
    const float* w_proj = (const float*)d_in[7];
    const float* b_proj = (const float*)d_in[8];
    const float* g2     = (const float*)d_in[9];
    const float* b2     = (const float*)d_in[10];
    const float* w_fc1  = (const float*)d_in[11];
    const float* b_fc1  = (const float*)d_in[12];
    const float* w_fc2  = (const float*)d_in[13];
    const float* b_fc2  = (const float*)d_in[14];
    float* out = (float*)d_out;

    __half *xw, *qkv, *attn, *x1, *xn2, *hbuf, *wall;
    float *bpre;
    cudaGetSymbolAddress((void**)&xw,   g_xw);
    cudaGetSymbolAddress((void**)&qkv,  g_qkv);
    cudaGetSymbolAddress((void**)&attn, g_attn);
    cudaGetSymbolAddress((void**)&x1,   g_x1);
    cudaGetSymbolAddress((void**)&xn2,  g_xn2);
    cudaGetSymbolAddress((void**)&hbuf, g_h);
    cudaGetSymbolAddress((void**)&wall, g_wall);
    cudaGetSymbolAddress((void**)&bpre, g_bias);

    __half* wq = wall + WOFF_QKV;
    __half* wp = wall + WOFF_PROJ;
    __half* w1 = wall + WOFF_FC1;
    __half* w2 = wall + WOFF_FC2;

    cudaFuncSetAttribute(gemm_kernel<768, 256, 0>,  cudaFuncAttributeMaxDynamicSharedMemorySize, GSMEM);
    cudaFuncSetAttribute(gemm_kernel<256, 256, 1>,  cudaFuncAttributeMaxDynamicSharedMemorySize, GSMEM);
    cudaFuncSetAttribute(gemm_kernel<1024, 256, 2>, cudaFuncAttributeMaxDynamicSharedMemorySize, GSMEM);
    cudaFuncSetAttribute(gemm_kernel<256, 1024, 3>, cudaFuncAttributeMaxDynamicSharedMemorySize, GSMEM);
    cudaFuncSetAttribute(attn_kernel, cudaFuncAttributeMaxDynamicSharedMemorySize, ATT_SMEM);

    cvt_all_kernel<<<WTOT / 8 / 256, 256>>>(w_qkv, w_proj, w_fc1, w_fc2, wall);
    bias_kernel<<<HEADS * 64 * 64 / 256, 256>>>(btab, bpre);
    ln_kernel<float, 1><<<TTOK / 8, 256>>>(x, g1, b1, xw);
    gemm_kernel<768, 256, 0><<<dim3(6, TTOK / 128), 256, GSMEM>>>(
        xw, wq, b_qkv, nullptr, nullptr, nullptr, qkv);
    attn_kernel<<<2048, 256, ATT_SMEM>>>(qkv, bpre, attn);
    gemm_kernel<256, 256, 1><<<dim3(2, TTOK / 128), 256, GSMEM>>>(
        attn, wp, b_proj, x, nullptr, nullptr, x1);
    ln_kernel<__half, 0><<<TTOK / 8, 256>>>(x1, g2, b2, xn2);
    gemm_kernel<1024, 256, 2><<<dim3(8, TTOK / 128), 256, GSMEM>>>(
        xn2, w1, b_fc1, nullptr, nullptr, nullptr, hbuf);
    gemm_kernel<256, 1024, 3><<<dim3(2, TTOK / 128), 256, GSMEM>>>(
        hbuf, w2, b_fc2, nullptr, x1, out, nullptr);
}

// round 15
// speedup vs baseline: 1.1337x; 1.0041x over previous
#include <cuda_runtime.h>
#include <cuda_fp16.h>
#include <math.h>
#include <stdint.h>

#define DIMC 256
#define HEADS 8
#define TTOK 131072          // 32*4096 tokens
#define HIDD 1024

// ---------------- scratch (static __device__, no allocs) ----------------
__device__ __align__(128) __half g_xw  [(size_t)TTOK * DIMC];     // swizzled, K=256
__device__ __align__(128) __half g_qkv [(size_t)TTOK * 3 * DIMC]; // LINEAR (attn input)
__device__ __align__(128) __half g_attn[(size_t)TTOK * DIMC];     // swizzled, K=256
__device__ __align__(128) __half g_x1  [(size_t)TTOK * DIMC];     // linear fp16, window order
__device__ __align__(128) __half g_xn2 [(size_t)TTOK * DIMC];     // swizzled, K=256
__device__ __align__(128) __half g_h   [(size_t)TTOK * HIDD];     // swizzled, K=1024
__device__ __align__(128) __half g_wall[(3 * DIMC + DIMC + HIDD + DIMC) * DIMC + DIMC * HIDD];
__device__ float g_bias[HEADS * 64 * 64];

#define WOFF_QKV  0
#define WOFF_PROJ (3 * DIMC * DIMC)
#define WOFF_FC1  (WOFF_PROJ + DIMC * DIMC)
#define WOFF_FC2  (WOFF_FC1 + HIDD * DIMC)
#define WTOT      (WOFF_FC2 + DIMC * HIDD)

// ---------------- PDL ----------------
#define PDL_TRIGGER() asm volatile("griddepcontrol.launch_dependents;" ::: "memory")
#define PDL_WAIT()    asm volatile("griddepcontrol.wait;" ::: "memory")

// ---------------- helpers ----------------
__device__ __forceinline__ uint32_t smem_u32(const void* p) {
    return (uint32_t)__cvta_generic_to_shared(p);
}
__device__ __forceinline__ void cp_async16(uint32_t saddr, const void* gptr) {
    asm volatile("cp.async.cg.shared.global [%0], [%1], 16;\n" :: "r"(saddr), "l"(gptr));
}
__device__ __forceinline__ void cp_commit() { asm volatile("cp.async.commit_group;\n"); }
__device__ __forceinline__ void bulk_g2s(uint32_t dst, const void* src, uint32_t bytes, uint32_t mbar) {
    asm volatile("cp.async.bulk.shared::cluster.global.mbarrier::complete_tx::bytes [%0], [%1], %2, [%3];"
                 :: "r"(dst), "l"(src), "r"(bytes), "r"(mbar) : "memory");
}
__device__ __forceinline__ void mbar_init(uint32_t mbar, uint32_t cnt) {
    asm volatile("mbarrier.init.shared.b64 [%0], %1;" :: "r"(mbar), "r"(cnt) : "memory");
}
__device__ __forceinline__ void mbar_expect_tx(uint32_t mbar, uint32_t bytes) {
    asm volatile("mbarrier.arrive.expect_tx.shared.b64 _, [%0], %1;" :: "r"(mbar), "r"(bytes) : "memory");
}
__device__ __forceinline__ void mbar_wait(uint32_t mbar, uint32_t parity) {
    asm volatile("{\n\t.reg .pred P1;\n\t"
                 "WAIT_%=:\n\t"
                 "mbarrier.try_wait.parity.acquire.cta.shared::cta.b64 P1, [%0], %1, 0x989680;\n\t"
                 "@P1 bra.uni DONE_%=;\n\t"
                 "bra.uni WAIT_%=;\n\t"
                 "DONE_%=:\n\t}"
                 :: "r"(mbar), "r"(parity) : "memory");
}
__device__ __forceinline__ void ldmatrix_x4(uint32_t& r0, uint32_t& r1, uint32_t& r2, uint32_t& r3, uint32_t addr) {
    asm volatile("ldmatrix.sync.aligned.m8n8.x4.shared.b16 {%0,%1,%2,%3}, [%4];\n"
                 : "=r"(r0), "=r"(r1), "=r"(r2), "=r"(r3) : "r"(addr));
}
__device__ __forceinline__ void ldmatrix_x2_trans(uint32_t& r0, uint32_t& r1, uint32_t addr) {
    asm volatile("ldmatrix.sync.aligned.m8n8.x2.trans.shared.b16 {%0,%1}, [%2];\n"
                 : "=r"(r0), "=r"(r1) : "r"(addr));
}
__device__ __forceinline__ void mma_f16acc(uint32_t c[2], const uint32_t a[4], const uint32_t b[2]) {
    asm volatile("mma.sync.aligned.m16n8k16.row.col.f16.f16.f16.f16 "
                 "{%0,%1}, {%2,%3,%4,%5}, {%6,%7}, {%0,%1};\n"
                 : "+r"(c[0]), "+r"(c[1])
                 : "r"(a[0]), "r"(a[1]), "r"(a[2]), "r"(a[3]), "r"(b[0]), "r"(b[1]));
}
__device__ __forceinline__ void mma_f32acc(float c[4], const uint32_t a[4], const uint32_t b[2]) {
    asm volatile("mma.sync.aligned.m16n8k16.row.col.f32.f16.f16.f32 "
                 "{%0,%1,%2,%3}, {%4,%5,%6,%7}, {%8,%9}, {%0,%1,%2,%3};\n"
                 : "+f"(c[0]), "+f"(c[1]), "+f"(c[2]), "+f"(c[3])
                 : "r"(a[0]), "r"(a[1]), "r"(a[2]), "r"(a[3]), "r"(b[0]), "r"(b[1]));
}
__device__ __forceinline__ float gelu_f(float v) {
    return 0.5f * v * (1.0f + erff(v * 0.7071067811865476f));
}
__device__ __forceinline__ int orig_to_win(int t) {
    int b = t >> 12, rem = t & 4095;
    int r = rem >> 6, c = rem & 63;
    int wi = (b << 6) + ((r >> 3) << 3) + (c >> 3);
    return (wi << 6) + ((r & 7) << 3) + (c & 7);
}
__device__ __forceinline__ int win_to_orig(int tw) {
    int wi = tw >> 6, k = tw & 63;
    int b = wi >> 6, w64 = wi & 63;
    int r = ((w64 >> 3) << 3) + (k >> 3);
    int c = ((w64 & 7) << 3) + (k & 7);
    return (b << 12) + (r << 6) + c;
}
__device__ __forceinline__ size_t swz_off(int row, int k, int Kd) {
    return ((size_t)((row >> 7) * (Kd >> 6) + (k >> 6)) << 14)
         + (size_t)((row & 127) * 128 + ((((k & 63) >> 3) ^ (row & 7)) << 4) + (k & 7) * 2);
}

// ---------------- fused weight convert -> swizzled fp16 tiles ----------------
__global__ void cvt_all_kernel(const float* __restrict__ wqkv, const float* __restrict__ wproj,
                               const float* __restrict__ wfc1, const float* __restrict__ wfc2,
                               __half* __restrict__ out) {
    PDL_TRIGGER();
    PDL_WAIT();
    int i = blockIdx.x * blockDim.x + threadIdx.x;
    int li = i * 8;
    const float* src; size_t basebyte; int Kd; int loc;
    if (li < WOFF_PROJ)      { src = wqkv;  loc = li;             basebyte = 0;                    Kd = 256; }
    else if (li < WOFF_FC1)  { src = wproj; loc = li - WOFF_PROJ; basebyte = (size_t)WOFF_PROJ*2;  Kd = 256; }
    else if (li < WOFF_FC2)  { src = wfc1;  loc = li - WOFF_FC1;  basebyte = (size_t)WOFF_FC1*2;   Kd = 256; }
    else                     { src = wfc2;  loc = li - WOFF_FC2;  basebyte = (size_t)WOFF_FC2*2;   Kd = 1024; }
    float4 a = *(const float4*)(src + loc);
    float4 b = *(const float4*)(src + loc + 4);
    int row = loc / Kd, k = loc % Kd;
    size_t off = basebyte + swz_off(row, k, Kd);
    __half2 p0 = __floats2half2_rn(a.x, a.y);
    __half2 p1 = __floats2half2_rn(a.z, a.w);
    __half2 p2 = __floats2half2_rn(b.x, b.y);
    __half2 p3 = __floats2half2_rn(b.z, b.w);
    uint4 pk;
    pk.x = *(uint32_t*)&p0; pk.y = *(uint32_t*)&p1; pk.z = *(uint32_t*)&p2; pk.w = *(uint32_t*)&p3;
    *(uint4*)((char*)out + off) = pk;
}

// ---------------- bias table precompute: g_bias[h][n][m] ----------------
__global__ void bias_kernel(const float* __restrict__ btab, float* __restrict__ bout) {
    PDL_TRIGGER();
    PDL_WAIT();
    int t = blockIdx.x * blockDim.x + threadIdx.x;
    int m = t & 63, n = (t >> 6) & 63, h = t >> 12;
    int rel = ((n >> 3) - (m >> 3) + 7) * 15 + ((n & 7) - (m & 7) + 7);
    bout[t] = btab[rel * 8 + h];
}

// ---------------- LayerNorm (warp per token), templated input, optional permute ----------------
template<typename TIN, int PERM>
__global__ __launch_bounds__(256) void ln_kernel(const TIN* __restrict__ x,
                                                 const float* __restrict__ g,
                                                 const float* __restrict__ b,
                                                 __half* __restrict__ out) {
    PDL_TRIGGER();
    PDL_WAIT();
    int warp = (blockIdx.x * 256 + threadIdx.x) >> 5;
    int lane = threadIdx.x & 31;
    float v[8];
    if constexpr (sizeof(TIN) == 4) {
        const float* row = (const float*)x + (size_t)warp * DIMC + lane * 8;
        float4 v0 = *(const float4*)row;
        float4 v1 = *(const float4*)(row + 4);
        v[0] = v0.x; v[1] = v0.y; v[2] = v0.z; v[3] = v0.w;
        v[4] = v1.x; v[5] = v1.y; v[6] = v1.z; v[7] = v1.w;
    } else {
        const __half* row = (const __half*)x + (size_t)warp * DIMC + lane * 8;
        uint4 pk = *(const uint4*)row;
        float2 f0 = __half22float2(*(__half2*)&pk.x);
        float2 f1 = __half22float2(*(__half2*)&pk.y);
        float2 f2 = __half22float2(*(__half2*)&pk.z);
        float2 f3 = __half22float2(*(__half2*)&pk.w);
        v[0] = f0.x; v[1] = f0.y; v[2] = f1.x; v[3] = f1.y;
        v[4] = f2.x; v[5] = f2.y; v[6] = f3.x; v[7] = f3.y;
    }
    float s = (v[0] + v[1]) + (v[2] + v[3]) + ((v[4] + v[5]) + (v[6] + v[7]));
#pragma unroll
    for (int o = 16; o; o >>= 1) s += __shfl_xor_sync(0xffffffffu, s, o);
    float mu = s * (1.0f / 256.0f);
    float d[8];
#pragma unroll
    for (int i = 0; i < 8; i++) d[i] = v[i] - mu;
    float ss = 0.f;
#pragma unroll
    for (int i = 0; i < 8; i++) ss += d[i] * d[i];
#pragma unroll
    for (int o = 16; o; o >>= 1) ss += __shfl_xor_sync(0xffffffffu, ss, o);
    float rstd = rsqrtf(ss * (1.0f / 256.0f) + 1e-5f);
    float4 gg0 = *(const float4*)(g + lane * 8);
    float4 gg1 = *(const float4*)(g + lane * 8 + 4);
    float4 bb0 = *(const float4*)(b + lane * 8);
    float4 bb1 = *(const float4*)(b + lane * 8 + 4);
    float y[8];
    y[0] = d[0] * rstd * gg0.x + bb0.x;  y[1] = d[1] * rstd * gg0.y + bb0.y;
    y[2] = d[2] * rstd * gg0.z + bb0.z;  y[3] = d[3] * rstd * gg0.w + bb0.w;
    y[4] = d[4] * rstd * gg1.x + bb1.x;  y[5] = d[5] * rstd * gg1.y + bb1.y;
    y[6] = d[6] * rstd * gg1.z + bb1.z;  y[7] = d[7] * rstd * gg1.w + bb1.w;
    int orow = PERM ? orig_to_win(warp) : warp;
    __half2 p0 = __floats2half2_rn(y[0], y[1]);
    __half2 p1 = __floats2half2_rn(y[2], y[3]);
    __half2 p2 = __floats2half2_rn(y[4], y[5]);
    __half2 p3 = __floats2half2_rn(y[6], y[7]);
    uint4 pk;
    pk.x = *(uint32_t*)&p0; pk.y = *(uint32_t*)&p1; pk.z = *(uint32_t*)&p2; pk.w = *(uint32_t*)&p3;
    *(uint4*)((char*)out + swz_off(orow, lane * 8, 256)) = pk;
}

// ---------------- fp16 TN GEMM (f16 accumulate), bulk tile loads ----------------
#define STG 32768
#define GSMEM (3 * STG + 64)

template<int N, int K, int EPI>
__global__ __launch_bounds__(256, 2) void gemm_kernel(const __half* __restrict__ A,
                                                      const __half* __restrict__ Bw,
                                                      const float* __restrict__ bias,
                                                      const float* __restrict__ resf,
                                                      const __half* __restrict__ res16,
                                                      float* __restrict__ outf,
                                                      __half* __restrict__ outb) {
    extern __shared__ __align__(128) uint8_t dynsm[];
    const int tid = threadIdx.x;
    const int lane = tid & 31;
    const int wid = tid >> 5;
    const int wm = wid & 3;
    const int wn = wid >> 2;
    const int m0 = blockIdx.y * 128;      // y = M
    const int n0 = blockIdx.x * 128;      // x = N (fast)
    const uint32_t sbase = smem_u32(dynsm);
    const uint32_t mb = sbase + 3 * STG;
    constexpr int KT = K / 64;

    PDL_TRIGGER();
    if (tid == 0) { mbar_init(mb, 1); mbar_init(mb + 8, 1); mbar_init(mb + 16, 1); }
    __syncthreads();
    PDL_WAIT();

    auto issue = [&](int kt) {
        uint32_t s = (uint32_t)(kt % 3);
        uint32_t mbs = mb + s * 8;
        mbar_expect_tx(mbs, 32768u);
        const char* srcA = (const char*)A + ((size_t)blockIdx.y * KT + kt) * 16384;
        const char* srcB = (const char*)Bw + ((size_t)blockIdx.x * KT + kt) * 16384;
        bulk_g2s(sbase + s * STG, srcA, 16384u, mbs);
        bulk_g2s(sbase + s * STG + 16384u, srcB, 16384u, mbs);
    };
    if (tid == 0) { issue(0); issue(1); }

    uint32_t acc[2][8][2];
#pragma unroll
    for (int a = 0; a < 2; a++)
#pragma unroll
        for (int bq = 0; bq < 8; bq++) { acc[a][bq][0] = 0u; acc[a][bq][1] = 0u; }

    const int ti = lane >> 3, rr = lane & 7;
#pragma unroll 1
    for (int kt = 0; kt < KT; kt++) {
        __syncthreads();
        if (tid == 0 && kt + 2 < KT) issue(kt + 2);
        mbar_wait(mb + (uint32_t)(kt % 3) * 8, (uint32_t)((kt / 3) & 1));
        uint32_t abase = sbase + (uint32_t)(kt % 3) * STG;
        uint32_t bbase = abase + 16384;
#pragma unroll
        for (int ks = 0; ks < 4; ks++) {
            int kcb = ks * 2;
            uint32_t afr[2][4];
#pragma unroll
            for (int mt = 0; mt < 2; mt++) {
                int row = wm * 32 + mt * 16 + ((ti & 1) ? 8 : 0) + rr;
                int kc = kcb + (ti >> 1);
                uint32_t addr = abase + ((((uint32_t)row << 3) | (uint32_t)(kc ^ (row & 7))) << 4);
                ldmatrix_x4(afr[mt][0], afr[mt][1], afr[mt][2], afr[mt][3], addr);
            }
            uint32_t bfr[8][2];
#pragma unroll
            for (int ng = 0; ng < 4; ng++) {
                int row = wn * 64 + ng * 16 + ((ti >> 1) ? 8 : 0) + rr;
                int kc = kcb + (ti & 1);
                uint32_t addr = bbase + ((((uint32_t)row << 3) | (uint32_t)(kc ^ (row & 7))) << 4);
                uint32_t r0, r1, r2, r3;
                ldmatrix_x4(r0, r1, r2, r3, addr);
                bfr[2 * ng][0] = r0;     bfr[2 * ng][1] = r1;
                bfr[2 * ng + 1][0] = r2; bfr[2 * ng + 1][1] = r3;
            }
#pragma unroll
            for (int mt = 0; mt < 2; mt++)
#pragma unroll
                for (int nt = 0; nt < 8; nt++)
                    mma_f16acc(acc[mt][nt], afr[mt], bfr[nt]);
        }
    }

    int lrow = lane >> 2, lc2 = (lane & 3) * 2;
#pragma unroll
    for (int mt = 0; mt < 2; mt++) {
#pragma unroll
        for (int hh = 0; hh < 2; hh++) {
            int r = m0 + wm * 32 + mt * 16 + lrow + hh * 8;
            if constexpr (EPI == 0) {
                __half* op = outb + (size_t)r * N;
#pragma unroll
                for (int nt = 0; nt < 8; nt++) {
                    int c = n0 + wn * 64 + nt * 8 + lc2;
                    float2 bb = *(const float2*)(bias + c);
                    float2 cv = __half22float2(*(__half2*)&acc[mt][nt][hh]);
                    *(__half2*)(op + c) = __floats2half2_rn(cv.x + bb.x, cv.y + bb.y);
                }
            } else if constexpr (EPI == 2) {
#pragma unroll
                for (int nt = 0; nt < 8; nt++) {
                    int c = n0 + wn * 64 + nt * 8 + lc2;
                    float2 bb = *(const float2*)(bias + c);
                    float2 cv = __half22float2(*(__half2*)&acc[mt][nt][hh]);
                    *(__half2*)((char*)outb + swz_off(r, c, 1024)) =
                        __floats2half2_rn(gelu_f(cv.x + bb.x), gelu_f(cv.y + bb.y));
                }
            } else if constexpr (EPI == 1) {
                int torig = win_to_orig(r);
                const float* xr = resf + (size_t)torig * 256;
                __half* op = outb + (size_t)r * 256;
#pragma unroll
                for (int nt = 0; nt < 8; nt++) {
                    int c = n0 + wn * 64 + nt * 8 + lc2;
                    float2 bb = *(const float2*)(bias + c);
                    float2 cv = __half22float2(*(__half2*)&acc[mt][nt][hh]);
                    float2 xres = *(const float2*)(xr + c);
                    *(__half2*)(op + c) = __floats2half2_rn(xres.x + cv.x + bb.x,
                                                            xres.y + cv.y + bb.y);
                }
            } else {
                int torig = win_to_orig(r);
                const __half* x1r = res16 + (size_t)r * 256;
                float* op = outf + (size_t)torig * 256;
#pragma unroll
                for (int nt = 0; nt < 8; nt++) {
                    int c = n0 + wn * 64 + nt * 8 + lc2;
                    float2 bb = *(const float2*)(bias + c);
                    float2 cv = __half22float2(*(__half2*)&acc[mt][nt][hh]);
                    float2 rr2 = __half22float2(*(const __half2*)(x1r + c));
                    *(float2*)(op + c) = make_float2(rr2.x + cv.x + bb.x, rr2.y + cv.y + bb.y);
                }
            }
        }
    }
}

// ---------------- windowed attention: fp16 in, f32 accum; swizzled fp16 out ----------------
#define ATT_PITCH 1552
#define ATT_SMEM (64 * ATT_PITCH)

__global__ __launch_bounds__(256, 2) void attn_kernel(const __half* __restrict__ qkv,
                                                      const float* __restrict__ bias_pre,
                                                      __half* __restrict__ out) {
    extern __shared__ __align__(128) uint8_t dynsm[];
    const int w = blockIdx.x;
    const int tid = threadIdx.x;
    const int h = tid >> 5, lane = tid & 31;
    const uint32_t sb = smem_u32(dynsm);
    const __half* gw = qkv + (size_t)w * 49152;

    PDL_TRIGGER();
    PDL_WAIT();
#pragma unroll
    for (int i = 0; i < 24; i++) {
        int ch = tid + i * 256;
        int r = ch / 96, c = ch % 96;
        cp_async16(sb + (uint32_t)(r * ATT_PITCH + c * 16), gw + r * 768 + c * 8);
    }
    cp_commit();
    asm volatile("cp.async.wait_group 0;\n" ::: "memory");
    __syncthreads();

    const uint32_t qbase = sb + (uint32_t)(h * 32) * 2;
    const uint32_t kbase = sb + (uint32_t)(256 + h * 32) * 2;
    const uint32_t vbase = sb + (uint32_t)(512 + h * 32) * 2;
    const float* bp = bias_pre + h * 4096;
    const float scale = 0.17677669529663688f;
    const int ti = lane >> 3, rr = lane & 7;
    const int lq = lane >> 2, lc = (lane & 3) * 2;

#pragma unroll 1
    for (int i = 0; i < 4; i++) {
        uint32_t qf[2][4];
#pragma unroll
        for (int ks = 0; ks < 2; ks++) {
            int row = i * 16 + ((ti & 1) ? 8 : 0) + rr;
            uint32_t addr = qbase + (uint32_t)(row * ATT_PITCH) + (uint32_t)((ks * 2 + (ti >> 1)) * 16);
            ldmatrix_x4(qf[ks][0], qf[ks][1], qf[ks][2], qf[ks][3], addr);
        }
        float sacc[8][4];
#pragma unroll
        for (int j = 0; j < 8; j++)
#pragma unroll
            for (int c = 0; c < 4; c++) sacc[j][c] = 0.f;
#pragma unroll
        for (int ks = 0; ks < 2; ks++) {
#pragma unroll
            for (int ng = 0; ng < 4; ng++) {
                int row = ng * 16 + ((ti >> 1) ? 8 : 0) + rr;
                uint32_t addr = kbase + (uint32_t)(row * ATT_PITCH) + (uint32_t)((ks * 2 + (ti & 1)) * 16);
                uint32_t b0, b1, b2, b3;
                ldmatrix_x4(b0, b1, b2, b3, addr);
                uint32_t bf0[2] = { b0, b1 }, bf1[2] = { b2, b3 };
                mma_f32acc(sacc[2 * ng],     qf[ks], bf0);
                mma_f32acc(sacc[2 * ng + 1], qf[ks], bf1);
            }
        }
        int r0 = i * 16 + lq, r1 = r0 + 8;
        float p[8][4];
        float mx0 = -1e30f, mx1 = -1e30f;
#pragma unroll
        for (int j = 0; j < 8; j++) {
            float2 b0 = *(const float2*)(bp + r0 * 64 + j * 8 + lc);
            float2 b1 = *(const float2*)(bp + r1 * 64 + j * 8 + lc);
            p[j][0] = fmaf(sacc[j][0], scale, b0.x);
            p[j][1] = fmaf(sacc[j][1], scale, b0.y);
            p[j][2] = fmaf(sacc[j][2], scale, b1.x);
            p[j][3] = fmaf(sacc[j][3], scale, b1.y);
            mx0 = fmaxf(mx0, fmaxf(p[j][0], p[j][1]));
            mx1 = fmaxf(mx1, fmaxf(p[j][2], p[j][3]));
        }
        mx0 = fmaxf(mx0, __shfl_xor_sync(0xffffffffu, mx0, 1));
        mx0 = fmaxf(mx0, __shfl_xor_sync(0xffffffffu, mx0, 2));
        mx1 = fmaxf(mx1, __shfl_xor_sync(0xffffffffu, mx1, 1));
        mx1 = fmaxf(mx1, __shfl_xor_sync(0xffffffffu, mx1, 2));
        float sm0 = 0.f, sm1 = 0.f;
#pragma unroll
        for (int j = 0; j < 8; j++) {
            p[j][0] = __expf(p[j][0] - mx0);
            p[j][1] = __expf(p[j][1] - mx0);
            p[j][2] = __expf(p[j][2] - mx1);
            p[j][3] = __expf(p[j][3] - mx1);
            sm0 += p[j][0] + p[j][1];
            sm1 += p[j][2] + p[j][3];
        }
        sm0 += __shfl_xor_sync(0xffffffffu, sm0, 1);
        sm0 += __shfl_xor_sync(0xffffffffu, sm0, 2);
        sm1 += __shfl_xor_sync(0xffffffffu, sm1, 1);
        sm1 += __shfl_xor_sync(0xffffffffu, sm1, 2);
        float inv0 = 1.0f / sm0, inv1 = 1.0f / sm1;

        uint32_t ap[4][4];
#pragma unroll
        for (int ks = 0; ks < 4; ks++) {
            __half2 t0 = __floats2half2_rn(p[2 * ks][0],     p[2 * ks][1]);
            __half2 t1 = __floats2half2_rn(p[2 * ks][2],     p[2 * ks][3]);
            __half2 t2 = __floats2half2_rn(p[2 * ks + 1][0], p[2 * ks + 1][1]);
            __half2 t3 = __floats2half2_rn(p[2 * ks + 1][2], p[2 * ks + 1][3]);
            ap[ks][0] = *(uint32_t*)&t0; ap[ks][1] = *(uint32_t*)&t1;
            ap[ks][2] = *(uint32_t*)&t2; ap[ks][3] = *(uint32_t*)&t3;
        }
        float o[4][4];
#pragma unroll
        for (int jj = 0; jj < 4; jj++)
#pragma unroll
            for (int c = 0; c < 4; c++) o[jj][c] = 0.f;
#pragma unroll
        for (int ks = 0; ks < 4; ks++) {
#pragma unroll
            for (int jj = 0; jj < 4; jj++) {
                uint32_t bv[2];
                uint32_t addr = vbase + (uint32_t)((ks * 16 + (lane & 15)) * ATT_PITCH) + (uint32_t)(jj * 16);
                ldmatrix_x2_trans(bv[0], bv[1], addr);
                mma_f32acc(o[jj], ap[ks], bv);
            }
        }
        int row0 = w * 64 + r0, row1 = w * 64 + r1;
#pragma unroll
        for (int jj = 0; jj < 4; jj++) {
            int k = h * 32 + jj * 8 + lc;
            *(__half2*)((char*)out + swz_off(row0, k, 256)) =
                __floats2half2_rn(o[jj][0] * inv0, o[jj][1] * inv0);
            *(__half2*)((char*)out + swz_off(row1, k, 256)) =
                __floats2half2_rn(o[jj][2] * inv1, o[jj][3] * inv1);
        }
    }
}

// ---------------- launch (PDL on the whole chain) ----------------
template<typename F, typename... Args>
static inline void launch_pdl(F f, dim3 grid, dim3 block, size_t smem, Args... args) {
    cudaLaunchConfig_t cfg = {};
    cfg.gridDim = grid;
    cfg.blockDim = block;
    cfg.dynamicSmemBytes = smem;
    cfg.stream = 0;
    cudaLaunchAttribute at[1];
    at[0].id = cudaLaunchAttributeProgrammaticStreamSerialization;
    at[0].val.programmaticStreamSerializationAllowed = 1;
    cfg.attrs = at;
    cfg.numAttrs = 1;
    cudaLaunchKernelEx(&cfg, f, args...);
}

extern "C" void kernel_launch(void* const* d_in, const int* in_sizes, int n_in,
                              void* d_out, int out_size) {
    const float* x      = (const float*)d_in[0];
    const float* g1     = (const float*)d_in[2];
    const float* b1     = (const float*)d_in[3];
    const float* w_qkv  = (const float*)d_in[4];
    const float* b_qkv  = (const float*)d_in[5];
    const float* btab   = (const float*)d_in[6];
    const float* w_proj = (const float*)d_in[7];
    const float* b_proj = (const float*)d_in[8];
    const float* g2     = (const float*)d_in[9];
    const float* b2     = (const float*)d_in[10];
    const float* w_fc1  = (const float*)d_in[11];
    const float* b_fc1  = (const float*)d_in[12];
    const float* w_fc2  = (const float*)d_in[13];
    const float* b_fc2  = (const float*)d_in[14];
    float* out = (float*)d_out;

    __half *xw, *qkv, *attn, *x1, *xn2, *hbuf, *wall;
    float *bpre;
    cudaGetSymbolAddress((void**)&xw,   g_xw);
    cudaGetSymbolAddress((void**)&qkv,  g_qkv);
    cudaGetSymbolAddress((void**)&attn, g_attn);
    cudaGetSymbolAddress((void**)&x1,   g_x1);
    cudaGetSymbolAddress((void**)&xn2,  g_xn2);
    cudaGetSymbolAddress((void**)&hbuf, g_h);
    cudaGetSymbolAddress((void**)&wall, g_wall);
    cudaGetSymbolAddress((void**)&bpre, g_bias);

    __half* wq = wall + WOFF_QKV;
    __half* wp = wall + WOFF_PROJ;
    __half* w1 = wall + WOFF_FC1;
    __half* w2 = wall + WOFF_FC2;

    cudaFuncSetAttribute(gemm_kernel<768, 256, 0>,  cudaFuncAttributeMaxDynamicSharedMemorySize, GSMEM);
    cudaFuncSetAttribute(gemm_kernel<256, 256, 1>,  cudaFuncAttributeMaxDynamicSharedMemorySize, GSMEM);
    cudaFuncSetAttribute(gemm_kernel<1024, 256, 2>, cudaFuncAttributeMaxDynamicSharedMemorySize, GSMEM);
    cudaFuncSetAttribute(gemm_kernel<256, 1024, 3>, cudaFuncAttributeMaxDynamicSharedMemorySize, GSMEM);
    cudaFuncSetAttribute(attn_kernel, cudaFuncAttributeMaxDynamicSharedMemorySize, ATT_SMEM);

    launch_pdl(cvt_all_kernel, dim3(WTOT / 8 / 256), dim3(256), 0,
               w_qkv, w_proj, w_fc1, w_fc2, wall);
    launch_pdl(bias_kernel, dim3(HEADS * 64 * 64 / 256), dim3(256), 0, btab, bpre);
    launch_pdl(ln_kernel<float, 1>, dim3(TTOK / 8), dim3(256), 0, x, g1, b1, xw);
    launch_pdl(gemm_kernel<768, 256, 0>, dim3(6, TTOK / 128), dim3(256), (size_t)GSMEM,
               (const __half*)xw, (const __half*)wq, b_qkv,
               (const float*)nullptr, (const __half*)nullptr, (float*)nullptr, qkv);
    launch_pdl(attn_kernel, dim3(2048), dim3(256), (size_t)ATT_SMEM,
               (const __half*)qkv, (const float*)bpre, attn);
    launch_pdl(gemm_kernel<256, 256, 1>, dim3(2, TTOK / 128), dim3(256), (size_t)GSMEM,
               (const __half*)attn, (const __half*)wp, b_proj,
               x, (const __half*)nullptr, (float*)nullptr, x1);
    launch_pdl(ln_kernel<__half, 0>, dim3(TTOK / 8), dim3(256), 0,
               (const __half*)x1, g2, b2, xn2);
    launch_pdl(gemm_kernel<1024, 256, 2>, dim3(8, TTOK / 128), dim3(256), (size_t)GSMEM,
               (const __half*)xn2, (const __half*)w1, b_fc1,
               (const float*)nullptr, (const __half*)nullptr, (float*)nullptr, hbuf);
    launch_pdl(gemm_kernel<256, 1024, 3>, dim3(2, TTOK / 128), dim3(256), (size_t)GSMEM,
               (const __half*)hbuf, (const __half*)w2, b_fc2,
               (const float*)nullptr, (const __half*)x1, out, (__half*)nullptr);
}

// round 16
// speedup vs baseline: 1.1341x; 1.0003x over previous
#include <cuda_runtime.h>
#include <cuda_fp16.h>
#include <math.h>
#include <stdint.h>

#define DIMC 256
#define HEADS 8
#define TTOK 131072          // 32*4096 tokens
#define HIDD 1024
#define MBLK (TTOK / 128)    // 1024 M-tiles

// ---------------- scratch (static __device__, no allocs) ----------------
__device__ __align__(128) __half g_xw  [(size_t)TTOK * DIMC];     // swizzled, K=256
__device__ __align__(128) __half g_qkv [(size_t)TTOK * 3 * DIMC]; // LINEAR (attn input)
__device__ __align__(128) __half g_attn[(size_t)TTOK * DIMC];     // swizzled, K=256
__device__ __align__(128) __half g_x1  [(size_t)TTOK * DIMC];     // linear fp16, window order
__device__ __align__(128) __half g_xn2 [(size_t)TTOK * DIMC];     // swizzled, K=256
__device__ __align__(128) __half g_h   [(size_t)TTOK * HIDD];     // swizzled, K=1024
__device__ __align__(128) __half g_wall[(3 * DIMC + DIMC + HIDD + DIMC) * DIMC + DIMC * HIDD];
__device__ float g_bias[HEADS * 64 * 64];

#define WOFF_QKV  0
#define WOFF_PROJ (3 * DIMC * DIMC)
#define WOFF_FC1  (WOFF_PROJ + DIMC * DIMC)
#define WOFF_FC2  (WOFF_FC1 + HIDD * DIMC)
#define WTOT      (WOFF_FC2 + DIMC * HIDD)

// ---------------- PDL ----------------
#define PDL_TRIGGER() asm volatile("griddepcontrol.launch_dependents;" ::: "memory")
#define PDL_WAIT()    asm volatile("griddepcontrol.wait;" ::: "memory")

// ---------------- helpers ----------------
__device__ __forceinline__ uint32_t smem_u32(const void* p) {
    return (uint32_t)__cvta_generic_to_shared(p);
}
__device__ __forceinline__ void cp_async16(uint32_t saddr, const void* gptr) {
    asm volatile("cp.async.cg.shared.global [%0], [%1], 16;\n" :: "r"(saddr), "l"(gptr));
}
__device__ __forceinline__ void cp_commit() { asm volatile("cp.async.commit_group;\n"); }
__device__ __forceinline__ void bulk_g2s(uint32_t dst, const void* src, uint32_t bytes, uint32_t mbar) {
    asm volatile("cp.async.bulk.shared::cluster.global.mbarrier::complete_tx::bytes [%0], [%1], %2, [%3];"
                 :: "r"(dst), "l"(src), "r"(bytes), "r"(mbar) : "memory");
}
__device__ __forceinline__ void mbar_init(uint32_t mbar, uint32_t cnt) {
    asm volatile("mbarrier.init.shared.b64 [%0], %1;" :: "r"(mbar), "r"(cnt) : "memory");
}
__device__ __forceinline__ void mbar_expect_tx(uint32_t mbar, uint32_t bytes) {
    asm volatile("mbarrier.arrive.expect_tx.shared.b64 _, [%0], %1;" :: "r"(mbar), "r"(bytes) : "memory");
}
__device__ __forceinline__ void mbar_wait(uint32_t mbar, uint32_t parity) {
    asm volatile("{\n\t.reg .pred P1;\n\t"
                 "WAIT_%=:\n\t"
                 "mbarrier.try_wait.parity.acquire.cta.shared::cta.b64 P1, [%0], %1, 0x989680;\n\t"
                 "@P1 bra.uni DONE_%=;\n\t"
                 "bra.uni WAIT_%=;\n\t"
                 "DONE_%=:\n\t}"
                 :: "r"(mbar), "r"(parity) : "memory");
}
__device__ __forceinline__ void ldmatrix_x4(uint32_t& r0, uint32_t& r1, uint32_t& r2, uint32_t& r3, uint32_t addr) {
    asm volatile("ldmatrix.sync.aligned.m8n8.x4.shared.b16 {%0,%1,%2,%3}, [%4];\n"
                 : "=r"(r0), "=r"(r1), "=r"(r2), "=r"(r3) : "r"(addr));
}
__device__ __forceinline__ void ldmatrix_x2_trans(uint32_t& r0, uint32_t& r1, uint32_t addr) {
    asm volatile("ldmatrix.sync.aligned.m8n8.x2.trans.shared.b16 {%0,%1}, [%2];\n"
                 : "=r"(r0), "=r"(r1) : "r"(addr));
}
__device__ __forceinline__ void mma_f16acc(uint32_t c[2], const uint32_t a[4], const uint32_t b[2]) {
    asm volatile("mma.sync.aligned.m16n8k16.row.col.f16.f16.f16.f16 "
                 "{%0,%1}, {%2,%3,%4,%5}, {%6,%7}, {%0,%1};\n"
                 : "+r"(c[0]), "+r"(c[1])
                 : "r"(a[0]), "r"(a[1]), "r"(a[2]), "r"(a[3]), "r"(b[0]), "r"(b[1]));
}
__device__ __forceinline__ void mma_f32acc(float c[4], const uint32_t a[4], const uint32_t b[2]) {
    asm volatile("mma.sync.aligned.m16n8k16.row.col.f32.f16.f16.f32 "
                 "{%0,%1,%2,%3}, {%4,%5,%6,%7}, {%8,%9}, {%0,%1,%2,%3};\n"
                 : "+f"(c[0]), "+f"(c[1]), "+f"(c[2]), "+f"(c[3])
                 : "r"(a[0]), "r"(a[1]), "r"(a[2]), "r"(a[3]), "r"(b[0]), "r"(b[1]));
}
__device__ __forceinline__ float gelu_f(float v) {
    return 0.5f * v * (1.0f + erff(v * 0.7071067811865476f));
}
__device__ __forceinline__ int orig_to_win(int t) {
    int b = t >> 12, rem = t & 4095;
    int r = rem >> 6, c = rem & 63;
    int wi = (b << 6) + ((r >> 3) << 3) + (c >> 3);
    return (wi << 6) + ((r & 7) << 3) + (c & 7);
}
__device__ __forceinline__ int win_to_orig(int tw) {
    int wi = tw >> 6, k = tw & 63;
    int b = wi >> 6, w64 = wi & 63;
    int r = ((w64 >> 3) << 3) + (k >> 3);
    int c = ((w64 & 7) << 3) + (k & 7);
    return (b << 12) + (r << 6) + c;
}
__device__ __forceinline__ size_t swz_off(int row, int k, int Kd) {
    return ((size_t)((row >> 7) * (Kd >> 6) + (k >> 6)) << 14)
         + (size_t)((row & 127) * 128 + ((((k & 63) >> 3) ^ (row & 7)) << 4) + (k & 7) * 2);
}

// ---------------- fused weight convert -> swizzled fp16 tiles ----------------
__global__ void cvt_all_kernel(const float* __restrict__ wqkv, const float* __restrict__ wproj,
                               const float* __restrict__ wfc1, const float* __restrict__ wfc2,
                               __half* __restrict__ out) {
    PDL_TRIGGER();
    PDL_WAIT();
    int i = blockIdx.x * blockDim.x + threadIdx.x;
    int li = i * 8;
    const float* src; size_t basebyte; int Kd; int loc;
    if (li < WOFF_PROJ)      { src = wqkv;  loc = li;             basebyte = 0;                    Kd = 256; }
    else if (li < WOFF_FC1)  { src = wproj; loc = li - WOFF_PROJ; basebyte = (size_t)WOFF_PROJ*2;  Kd = 256; }
    else if (li < WOFF_FC2)  { src = wfc1;  loc = li - WOFF_FC1;  basebyte = (size_t)WOFF_FC1*2;   Kd = 256; }
    else                     { src = wfc2;  loc = li - WOFF_FC2;  basebyte = (size_t)WOFF_FC2*2;   Kd = 1024; }
    float4 a = *(const float4*)(src + loc);
    float4 b = *(const float4*)(src + loc + 4);
    int row = loc / Kd, k = loc % Kd;
    size_t off = basebyte + swz_off(row, k, Kd);
    __half2 p0 = __floats2half2_rn(a.x, a.y);
    __half2 p1 = __floats2half2_rn(a.z, a.w);
    __half2 p2 = __floats2half2_rn(b.x, b.y);
    __half2 p3 = __floats2half2_rn(b.z, b.w);
    uint4 pk;
    pk.x = *(uint32_t*)&p0; pk.y = *(uint32_t*)&p1; pk.z = *(uint32_t*)&p2; pk.w = *(uint32_t*)&p3;
    *(uint4*)((char*)out + off) = pk;
}

// ---------------- bias table precompute: g_bias[h][n][m] ----------------
__global__ void bias_kernel(const float* __restrict__ btab, float* __restrict__ bout) {
    PDL_TRIGGER();
    PDL_WAIT();
    int t = blockIdx.x * blockDim.x + threadIdx.x;
    int m = t & 63, n = (t >> 6) & 63, h = t >> 12;
    int rel = ((n >> 3) - (m >> 3) + 7) * 15 + ((n & 7) - (m & 7) + 7);
    bout[t] = btab[rel * 8 + h];
}

// ---------------- LayerNorm (warp per token), templated input, optional permute ----------------
template<typename TIN, int PERM>
__global__ __launch_bounds__(256) void ln_kernel(const TIN* __restrict__ x,
                                                 const float* __restrict__ g,
                                                 const float* __restrict__ b,
                                                 __half* __restrict__ out) {
    PDL_TRIGGER();
    PDL_WAIT();
    int warp = (blockIdx.x * 256 + threadIdx.x) >> 5;
    int lane = threadIdx.x & 31;
    float v[8];
    if constexpr (sizeof(TIN) == 4) {
        const float* row = (const float*)x + (size_t)warp * DIMC + lane * 8;
        float4 v0 = *(const float4*)row;
        float4 v1 = *(const float4*)(row + 4);
        v[0] = v0.x; v[1] = v0.y; v[2] = v0.z; v[3] = v0.w;
        v[4] = v1.x; v[5] = v1.y; v[6] = v1.z; v[7] = v1.w;
    } else {
        const __half* row = (const __half*)x + (size_t)warp * DIMC + lane * 8;
        uint4 pk = *(const uint4*)row;
        float2 f0 = __half22float2(*(__half2*)&pk.x);
        float2 f1 = __half22float2(*(__half2*)&pk.y);
        float2 f2 = __half22float2(*(__half2*)&pk.z);
        float2 f3 = __half22float2(*(__half2*)&pk.w);
        v[0] = f0.x; v[1] = f0.y; v[2] = f1.x; v[3] = f1.y;
        v[4] = f2.x; v[5] = f2.y; v[6] = f3.x; v[7] = f3.y;
    }
    float s = (v[0] + v[1]) + (v[2] + v[3]) + ((v[4] + v[5]) + (v[6] + v[7]));
#pragma unroll
    for (int o = 16; o; o >>= 1) s += __shfl_xor_sync(0xffffffffu, s, o);
    float mu = s * (1.0f / 256.0f);
    float d[8];
#pragma unroll
    for (int i = 0; i < 8; i++) d[i] = v[i] - mu;
    float ss = 0.f;
#pragma unroll
    for (int i = 0; i < 8; i++) ss += d[i] * d[i];
#pragma unroll
    for (int o = 16; o; o >>= 1) ss += __shfl_xor_sync(0xffffffffu, ss, o);
    float rstd = rsqrtf(ss * (1.0f / 256.0f) + 1e-5f);
    float4 gg0 = *(const float4*)(g + lane * 8);
    float4 gg1 = *(const float4*)(g + lane * 8 + 4);
    float4 bb0 = *(const float4*)(b + lane * 8);
    float4 bb1 = *(const float4*)(b + lane * 8 + 4);
    float y[8];
    y[0] = d[0] * rstd * gg0.x + bb0.x;  y[1] = d[1] * rstd * gg0.y + bb0.y;
    y[2] = d[2] * rstd * gg0.z + bb0.z;  y[3] = d[3] * rstd * gg0.w + bb0.w;
    y[4] = d[4] * rstd * gg1.x + bb1.x;  y[5] = d[5] * rstd * gg1.y + bb1.y;
    y[6] = d[6] * rstd * gg1.z + bb1.z;  y[7] = d[7] * rstd * gg1.w + bb1.w;
    int orow = PERM ? orig_to_win(warp) : warp;
    __half2 p0 = __floats2half2_rn(y[0], y[1]);
    __half2 p1 = __floats2half2_rn(y[2], y[3]);
    __half2 p2 = __floats2half2_rn(y[4], y[5]);
    __half2 p3 = __floats2half2_rn(y[6], y[7]);
    uint4 pk;
    pk.x = *(uint32_t*)&p0; pk.y = *(uint32_t*)&p1; pk.z = *(uint32_t*)&p2; pk.w = *(uint32_t*)&p3;
    *(uint4*)((char*)out + swz_off(orow, lane * 8, 256)) = pk;
}

// ---------------- PERSISTENT fp16 TN GEMM (f16 accumulate), continuous bulk ring ----------------
// Grid = 2*SMs persistent CTAs; each loops tiles t = cta, cta+G, ... (N fast-varying).
// 3-stage ring with global issue/consume counters carried across tiles.
#define STG 32768
#define GSMEM (3 * STG + 64)

template<int N, int K, int EPI>
__global__ __launch_bounds__(256, 2) void gemm_kernel(const __half* __restrict__ A,
                                                      const __half* __restrict__ Bw,
                                                      const float* __restrict__ bias,
                                                      const float* __restrict__ resf,
                                                      const __half* __restrict__ res16,
                                                      float* __restrict__ outf,
                                                      __half* __restrict__ outb) {
    extern __shared__ __align__(128) uint8_t dynsm[];
    const int tid = threadIdx.x;
    const int lane = tid & 31;
    const int wid = tid >> 5;
    const int wm = wid & 3;
    const int wn = wid >> 2;
    const uint32_t sbase = smem_u32(dynsm);
    const uint32_t mb = sbase + 3 * STG;
    constexpr int KT = K / 64;
    constexpr int NB = N / 128;
    constexpr int TT = MBLK * NB;
    const int G = gridDim.x;

    PDL_TRIGGER();
    if (tid == 0) { mbar_init(mb, 1); mbar_init(mb + 8, 1); mbar_init(mb + 16, 1); }
    __syncthreads();
    PDL_WAIT();

    // issue-side state (only tid 0 uses; lambda captures by ref)
    int jt = blockIdx.x;     // tile being issued
    int ikt = 0;             // k-chunk within that tile
    int icnt = 0;            // global issued-chunk count
    auto issue_next = [&]() {
        int m_blk = jt / NB, n_blk = jt - m_blk * NB;
        uint32_t s = (uint32_t)(icnt % 3);
        uint32_t mbs = mb + s * 8;
        mbar_expect_tx(mbs, 32768u);
        bulk_g2s(sbase + s * STG,
                 (const char*)A + ((size_t)m_blk * KT + ikt) * 16384, 16384u, mbs);
        bulk_g2s(sbase + s * STG + 16384u,
                 (const char*)Bw + ((size_t)n_blk * KT + ikt) * 16384, 16384u, mbs);
        icnt++;
        if (++ikt == KT) { ikt = 0; jt += G; }
    };
    if (tid == 0) { issue_next(); issue_next(); }

    const int ti = lane >> 3, rr = lane & 7;
    const int lrow = lane >> 2, lc2 = (lane & 3) * 2;
    int ccnt = 0;            // global consumed-chunk count

#pragma unroll 1
    for (int t = blockIdx.x; t < TT; t += G) {
        const int m0 = (t / NB) * 128;
        const int n0 = (t - (t / NB) * NB) * 128;

        uint32_t acc[2][8][2];
#pragma unroll
        for (int a = 0; a < 2; a++)
#pragma unroll
            for (int bq = 0; bq < 8; bq++) { acc[a][bq][0] = 0u; acc[a][bq][1] = 0u; }

#pragma unroll 1
        for (int kt = 0; kt < KT; kt++) {
            __syncthreads();
            if (tid == 0 && jt < TT) issue_next();
            mbar_wait(mb + (uint32_t)(ccnt % 3) * 8, (uint32_t)((ccnt / 3) & 1));
            uint32_t abase = sbase + (uint32_t)(ccnt % 3) * STG;
            uint32_t bbase = abase + 16384;
#pragma unroll
            for (int ks = 0; ks < 4; ks++) {
                int kcb = ks * 2;
                uint32_t afr[2][4];
#pragma unroll
                for (int mt = 0; mt < 2; mt++) {
                    int row = wm * 32 + mt * 16 + ((ti & 1) ? 8 : 0) + rr;
                    int kc = kcb + (ti >> 1);
                    uint32_t addr = abase + ((((uint32_t)row << 3) | (uint32_t)(kc ^ (row & 7))) << 4);
                    ldmatrix_x4(afr[mt][0], afr[mt][1], afr[mt][2], afr[mt][3], addr);
                }
                uint32_t bfr[8][2];
#pragma unroll
                for (int ng = 0; ng < 4; ng++) {
                    int row = wn * 64 + ng * 16 + ((ti >> 1) ? 8 : 0) + rr;
                    int kc = kcb + (ti & 1);
                    uint32_t addr = bbase + ((((uint32_t)row << 3) | (uint32_t)(kc ^ (row & 7))) << 4);
                    uint32_t r0, r1, r2, r3;
                    ldmatrix_x4(r0, r1, r2, r3, addr);
                    bfr[2 * ng][0] = r0;     bfr[2 * ng][1] = r1;
                    bfr[2 * ng + 1][0] = r2; bfr[2 * ng + 1][1] = r3;
                }
#pragma unroll
                for (int mt = 0; mt < 2; mt++)
#pragma unroll
                    for (int nt = 0; nt < 8; nt++)
                        mma_f16acc(acc[mt][nt], afr[mt], bfr[nt]);
            }
            ccnt++;
        }

        // -------- epilogue for tile t --------
#pragma unroll
        for (int mt = 0; mt < 2; mt++) {
#pragma unroll
            for (int hh = 0; hh < 2; hh++) {
                int r = m0 + wm * 32 + mt * 16 + lrow + hh * 8;
                if constexpr (EPI == 0) {
                    __half* op = outb + (size_t)r * N;
#pragma unroll
                    for (int nt = 0; nt < 8; nt++) {
                        int c = n0 + wn * 64 + nt * 8 + lc2;
                        float2 bb = *(const float2*)(bias + c);
                        float2 cv = __half22float2(*(__half2*)&acc[mt][nt][hh]);
                        *(__half2*)(op + c) = __floats2half2_rn(cv.x + bb.x, cv.y + bb.y);
                    }
                } else if constexpr (EPI == 2) {
#pragma unroll
                    for (int nt = 0; nt < 8; nt++) {
                        int c = n0 + wn * 64 + nt * 8 + lc2;
                        float2 bb = *(const float2*)(bias + c);
                        float2 cv = __half22float2(*(__half2*)&acc[mt][nt][hh]);
                        *(__half2*)((char*)outb + swz_off(r, c, 1024)) =
                            __floats2half2_rn(gelu_f(cv.x + bb.x), gelu_f(cv.y + bb.y));
                    }
                } else if constexpr (EPI == 1) {
                    int torig = win_to_orig(r);
                    const float* xr = resf + (size_t)torig * 256;
                    __half* op = outb + (size_t)r * 256;
#pragma unroll
                    for (int nt = 0; nt < 8; nt++) {
                        int c = n0 + wn * 64 + nt * 8 + lc2;
                        float2 bb = *(const float2*)(bias + c);
                        float2 cv = __half22float2(*(__half2*)&acc[mt][nt][hh]);
                        float2 xres = *(const float2*)(xr + c);
                        *(__half2*)(op + c) = __floats2half2_rn(xres.x + cv.x + bb.x,
                                                                xres.y + cv.y + bb.y);
                    }
                } else {
                    int torig = win_to_orig(r);
                    const __half* x1r = res16 + (size_t)r * 256;
                    float* op = outf + (size_t)torig * 256;
#pragma unroll
                    for (int nt = 0; nt < 8; nt++) {
                        int c = n0 + wn * 64 + nt * 8 + lc2;
                        float2 bb = *(const float2*)(bias + c);
                        float2 cv = __half22float2(*(__half2*)&acc[mt][nt][hh]);
                        float2 rr2 = __half22float2(*(const __half2*)(x1r + c));
                        *(float2*)(op + c) = make_float2(rr2.x + cv.x + bb.x, rr2.y + cv.y + bb.y);
                    }
                }
            }
        }
    }
}

// ---------------- windowed attention: fp16 in, f32 accum; swizzled fp16 out ----------------
#define ATT_PITCH 1552
#define ATT_SMEM (64 * ATT_PITCH)

__global__ __launch_bounds__(256, 2) void attn_kernel(const __half* __restrict__ qkv,
                                                      const float* __restrict__ bias_pre,
                                                      __half* __restrict__ out) {
    extern __shared__ __align__(128) uint8_t dynsm[];
    const int w = blockIdx.x;
    const int tid = threadIdx.x;
    const int h = tid >> 5, lane = tid & 31;
    const uint32_t sb = smem_u32(dynsm);
    const __half* gw = qkv + (size_t)w * 49152;

    PDL_TRIGGER();
    PDL_WAIT();
#pragma unroll
    for (int i = 0; i < 24; i++) {
        int ch = tid + i * 256;
        int r = ch / 96, c = ch % 96;
        cp_async16(sb + (uint32_t)(r * ATT_PITCH + c * 16), gw + r * 768 + c * 8);
    }
    cp_commit();
    asm volatile("cp.async.wait_group 0;\n" ::: "memory");
    __syncthreads();

    const uint32_t qbase = sb + (uint32_t)(h * 32) * 2;
    const uint32_t kbase = sb + (uint32_t)(256 + h * 32) * 2;
    const uint32_t vbase = sb + (uint32_t)(512 + h * 32) * 2;
    const float* bp = bias_pre + h * 4096;
    const float scale = 0.17677669529663688f;
    const int ti = lane >> 3, rr = lane & 7;
    const int lq = lane >> 2, lc = (lane & 3) * 2;

#pragma unroll 1
    for (int i = 0; i < 4; i++) {
        uint32_t qf[2][4];
#pragma unroll
        for (int ks = 0; ks < 2; ks++) {
            int row = i * 16 + ((ti & 1) ? 8 : 0) + rr;
            uint32_t addr = qbase + (uint32_t)(row * ATT_PITCH) + (uint32_t)((ks * 2 + (ti >> 1)) * 16);
            ldmatrix_x4(qf[ks][0], qf[ks][1], qf[ks][2], qf[ks][3], addr);
        }
        float sacc[8][4];
#pragma unroll
        for (int j = 0; j < 8; j++)
#pragma unroll
            for (int c = 0; c < 4; c++) sacc[j][c] = 0.f;
#pragma unroll
        for (int ks = 0; ks < 2; ks++) {
#pragma unroll
            for (int ng = 0; ng < 4; ng++) {
                int row = ng * 16 + ((ti >> 1) ? 8 : 0) + rr;
                uint32_t addr = kbase + (uint32_t)(row * ATT_PITCH) + (uint32_t)((ks * 2 + (ti & 1)) * 16);
                uint32_t b0, b1, b2, b3;
                ldmatrix_x4(b0, b1, b2, b3, addr);
                uint32_t bf0[2] = { b0, b1 }, bf1[2] = { b2, b3 };
                mma_f32acc(sacc[2 * ng],     qf[ks], bf0);
                mma_f32acc(sacc[2 * ng + 1], qf[ks], bf1);
            }
        }
        int r0 = i * 16 + lq, r1 = r0 + 8;
        float p[8][4];
        float mx0 = -1e30f, mx1 = -1e30f;
#pragma unroll
        for (int j = 0; j < 8; j++) {
            float2 b0 = *(const float2*)(bp + r0 * 64 + j * 8 + lc);
            float2 b1 = *(const float2*)(bp + r1 * 64 + j * 8 + lc);
            p[j][0] = fmaf(sacc[j][0], scale, b0.x);
            p[j][1] = fmaf(sacc[j][1], scale, b0.y);
            p[j][2] = fmaf(sacc[j][2], scale, b1.x);
            p[j][3] = fmaf(sacc[j][3], scale, b1.y);
            mx0 = fmaxf(mx0, fmaxf(p[j][0], p[j][1]));
            mx1 = fmaxf(mx1, fmaxf(p[j][2], p[j][3]));
        }
        mx0 = fmaxf(mx0, __shfl_xor_sync(0xffffffffu, mx0, 1));
        mx0 = fmaxf(mx0, __shfl_xor_sync(0xffffffffu, mx0, 2));
        mx1 = fmaxf(mx1, __shfl_xor_sync(0xffffffffu, mx1, 1));
        mx1 = fmaxf(mx1, __shfl_xor_sync(0xffffffffu, mx1, 2));
        float sm0 = 0.f, sm1 = 0.f;
#pragma unroll
        for (int j = 0; j < 8; j++) {
            p[j][0] = __expf(p[j][0] - mx0);
            p[j][1] = __expf(p[j][1] - mx0);
            p[j][2] = __expf(p[j][2] - mx1);
            p[j][3] = __expf(p[j][3] - mx1);
            sm0 += p[j][0] + p[j][1];
            sm1 += p[j][2] + p[j][3];
        }
        sm0 += __shfl_xor_sync(0xffffffffu, sm0, 1);
        sm0 += __shfl_xor_sync(0xffffffffu, sm0, 2);
        sm1 += __shfl_xor_sync(0xffffffffu, sm1, 1);
        sm1 += __shfl_xor_sync(0xffffffffu, sm1, 2);
        float inv0 = 1.0f / sm0, inv1 = 1.0f / sm1;

        uint32_t ap[4][4];
#pragma unroll
        for (int ks = 0; ks < 4; ks++) {
            __half2 t0 = __floats2half2_rn(p[2 * ks][0],     p[2 * ks][1]);
            __half2 t1 = __floats2half2_rn(p[2 * ks][2],     p[2 * ks][3]);
            __half2 t2 = __floats2half2_rn(p[2 * ks + 1][0], p[2 * ks + 1][1]);
            __half2 t3 = __floats2half2_rn(p[2 * ks + 1][2], p[2 * ks + 1][3]);
            ap[ks][0] = *(uint32_t*)&t0; ap[ks][1] = *(uint32_t*)&t1;
            ap[ks][2] = *(uint32_t*)&t2; ap[ks][3] = *(uint32_t*)&t3;
        }
        float o[4][4];
#pragma unroll
        for (int jj = 0; jj < 4; jj++)
#pragma unroll
            for (int c = 0; c < 4; c++) o[jj][c] = 0.f;
#pragma unroll
        for (int ks = 0; ks < 4; ks++) {
#pragma unroll
            for (int jj = 0; jj < 4; jj++) {
                uint32_t bv[2];
                uint32_t addr = vbase + (uint32_t)((ks * 16 + (lane & 15)) * ATT_PITCH) + (uint32_t)(jj * 16);
                ldmatrix_x2_trans(bv[0], bv[1], addr);
                mma_f32acc(o[jj], ap[ks], bv);
            }
        }
        int row0 = w * 64 + r0, row1 = w * 64 + r1;
#pragma unroll
        for (int jj = 0; jj < 4; jj++) {
            int k = h * 32 + jj * 8 + lc;
            *(__half2*)((char*)out + swz_off(row0, k, 256)) =
                __floats2half2_rn(o[jj][0] * inv0, o[jj][1] * inv0);
            *(__half2*)((char*)out + swz_off(row1, k, 256)) =
                __floats2half2_rn(o[jj][2] * inv1, o[jj][3] * inv1);
        }
    }
}

// ---------------- launch (PDL on the whole chain) ----------------
template<typename F, typename... Args>
static inline void launch_pdl(F f, dim3 grid, dim3 block, size_t smem, Args... args) {
    cudaLaunchConfig_t cfg = {};
    cfg.gridDim = grid;
    cfg.blockDim = block;
    cfg.dynamicSmemBytes = smem;
    cfg.stream = 0;
    cudaLaunchAttribute at[1];
    at[0].id = cudaLaunchAttributeProgrammaticStreamSerialization;
    at[0].val.programmaticStreamSerializationAllowed = 1;
    cfg.attrs = at;
    cfg.numAttrs = 1;
    cudaLaunchKernelEx(&cfg, f, args...);
}

extern "C" void kernel_launch(void* const* d_in, const int* in_sizes, int n_in,
                              void* d_out, int out_size) {
    const float* x      = (const float*)d_in[0];
    const float* g1     = (const float*)d_in[2];
    const float* b1     = (const float*)d_in[3];
    const float* w_qkv  = (const float*)d_in[4];
    const float* b_qkv  = (const float*)d_in[5];
    const float* btab   = (const float*)d_in[6];
    const float* w_proj = (const float*)d_in[7];
    const float* b_proj = (const float*)d_in[8];
    const float* g2     = (const float*)d_in[9];
    const float* b2     = (const float*)d_in[10];
    const float* w_fc1  = (const float*)d_in[11];
    const float* b_fc1  = (const float*)d_in[12];
    const float* w_fc2  = (const float*)d_in[13];
    const float* b_fc2  = (const float*)d_in[14];
    float* out = (float*)d_out;

    __half *xw, *qkv, *attn, *x1, *xn2, *hbuf, *wall;
    float *bpre;
    cudaGetSymbolAddress((void**)&xw,   g_xw);
    cudaGetSymbolAddress((void**)&qkv,  g_qkv);
    cudaGetSymbolAddress((void**)&attn, g_attn);
    cudaGetSymbolAddress((void**)&x1,   g_x1);
    cudaGetSymbolAddress((void**)&xn2,  g_xn2);
    cudaGetSymbolAddress((void**)&hbuf, g_h);
    cudaGetSymbolAddress((void**)&wall, g_wall);
    cudaGetSymbolAddress((void**)&bpre, g_bias);

    __half* wq = wall + WOFF_QKV;
    __half* wp = wall + WOFF_PROJ;
    __half* w1 = wall + WOFF_FC1;
    __half* w2 = wall + WOFF_FC2;

    int nsm = 148;
    cudaDeviceGetAttribute(&nsm, cudaDevAttrMultiProcessorCount, 0);
    const int G = 2 * nsm;

    cudaFuncSetAttribute(gemm_kernel<768, 256, 0>,  cudaFuncAttributeMaxDynamicSharedMemorySize, GSMEM);
    cudaFuncSetAttribute(gemm_kernel<256, 256, 1>,  cudaFuncAttributeMaxDynamicSharedMemorySize, GSMEM);
    cudaFuncSetAttribute(gemm_kernel<1024, 256, 2>, cudaFuncAttributeMaxDynamicSharedMemorySize, GSMEM);
    cudaFuncSetAttribute(gemm_kernel<256, 1024, 3>, cudaFuncAttributeMaxDynamicSharedMemorySize, GSMEM);
    cudaFuncSetAttribute(attn_kernel, cudaFuncAttributeMaxDynamicSharedMemorySize, ATT_SMEM);

    launch_pdl(cvt_all_kernel, dim3(WTOT / 8 / 256), dim3(256), 0,
               w_qkv, w_proj, w_fc1, w_fc2, wall);
    launch_pdl(bias_kernel, dim3(HEADS * 64 * 64 / 256), dim3(256), 0, btab, bpre);
    launch_pdl(ln_kernel<float, 1>, dim3(TTOK / 8), dim3(256), 0, x, g1, b1, xw);
    launch_pdl(gemm_kernel<768, 256, 0>, dim3(G), dim3(256), (size_t)GSMEM,
               (const __half*)xw, (const __half*)wq, b_qkv,
               (const float*)nullptr, (const __half*)nullptr, (float*)nullptr, qkv);
    launch_pdl(attn_kernel, dim3(2048), dim3(256), (size_t)ATT_SMEM,
               (const __half*)qkv, (const float*)bpre, attn);
    launch_pdl(gemm_kernel<256, 256, 1>, dim3(G), dim3(256), (size_t)GSMEM,
               (const __half*)attn, (const __half*)wp, b_proj,
               x, (const __half*)nullptr, (float*)nullptr, x1);
    launch_pdl(ln_kernel<__half, 0>, dim3(TTOK / 8), dim3(256), 0,
               (const __half*)x1, g2, b2, xn2);
    launch_pdl(gemm_kernel<1024, 256, 2>, dim3(G), dim3(256), (size_t)GSMEM,
               (const __half*)xn2, (const __half*)w1, b_fc1,
               (const float*)nullptr, (const __half*)nullptr, (float*)nullptr, hbuf);
    launch_pdl(gemm_kernel<256, 1024, 3>, dim3(G), dim3(256), (size_t)GSMEM,
               (const __half*)hbuf, (const __half*)w2, b_fc2,
               (const float*)nullptr, (const __half*)x1, out, (__half*)nullptr);
}

// round 17
// speedup vs baseline: 1.1781x; 1.0388x over previous
#include <cuda_runtime.h>
#include <cuda_fp16.h>
#include <math.h>
#include <stdint.h>

#define DIMC 256
#define HEADS 8
#define TTOK 131072          // 32*4096 tokens
#define HTOK (TTOK / 2)      // tokens per half (batch-aligned: 16 batches)
#define HIDD 1024
#define HMT (HTOK / 128)     // 512 M-tiles per half

// ---------------- scratch (static __device__, no allocs) ----------------
__device__ __align__(128) __half g_xw  [(size_t)TTOK * DIMC];     // swizzled, K=256
__device__ __align__(128) __half g_qkv [(size_t)TTOK * 3 * DIMC]; // LINEAR (attn input)
__device__ __align__(128) __half g_attn[(size_t)TTOK * DIMC];     // swizzled, K=256
__device__ __align__(128) __half g_x1  [(size_t)TTOK * DIMC];     // linear fp16, window order
__device__ __align__(128) __half g_xn2 [(size_t)TTOK * DIMC];     // swizzled, K=256
__device__ __align__(128) __half g_h   [(size_t)TTOK * HIDD];     // swizzled, K=1024
__device__ __align__(128) __half g_wall[(3 * DIMC + DIMC + HIDD + DIMC) * DIMC + DIMC * HIDD];
__device__ float g_bias[HEADS * 64 * 64];

#define WOFF_QKV  0
#define WOFF_PROJ (3 * DIMC * DIMC)
#define WOFF_FC1  (WOFF_PROJ + DIMC * DIMC)
#define WOFF_FC2  (WOFF_FC1 + HIDD * DIMC)
#define WTOT      (WOFF_FC2 + DIMC * HIDD)

// ---------------- PDL ----------------
#define PDL_TRIGGER() asm volatile("griddepcontrol.launch_dependents;" ::: "memory")
#define PDL_WAIT()    asm volatile("griddepcontrol.wait;" ::: "memory")

// ---------------- helpers ----------------
__device__ __forceinline__ uint32_t smem_u32(const void* p) {
    return (uint32_t)__cvta_generic_to_shared(p);
}
__device__ __forceinline__ void cp_async16(uint32_t saddr, const void* gptr) {
    asm volatile("cp.async.cg.shared.global [%0], [%1], 16;\n" :: "r"(saddr), "l"(gptr));
}
__device__ __forceinline__ void cp_commit() { asm volatile("cp.async.commit_group;\n"); }
__device__ __forceinline__ void bulk_g2s(uint32_t dst, const void* src, uint32_t bytes, uint32_t mbar) {
    asm volatile("cp.async.bulk.shared::cluster.global.mbarrier::complete_tx::bytes [%0], [%1], %2, [%3];"
                 :: "r"(dst), "l"(src), "r"(bytes), "r"(mbar) : "memory");
}
__device__ __forceinline__ void mbar_init(uint32_t mbar, uint32_t cnt) {
    asm volatile("mbarrier.init.shared.b64 [%0], %1;" :: "r"(mbar), "r"(cnt) : "memory");
}
__device__ __forceinline__ void mbar_expect_tx(uint32_t mbar, uint32_t bytes) {
    asm volatile("mbarrier.arrive.expect_tx.shared.b64 _, [%0], %1;" :: "r"(mbar), "r"(bytes) : "memory");
}
__device__ __forceinline__ void mbar_wait(uint32_t mbar, uint32_t parity) {
    asm volatile("{\n\t.reg .pred P1;\n\t"
                 "WAIT_%=:\n\t"
                 "mbarrier.try_wait.parity.acquire.cta.shared::cta.b64 P1, [%0], %1, 0x989680;\n\t"
                 "@P1 bra.uni DONE_%=;\n\t"
                 "bra.uni WAIT_%=;\n\t"
                 "DONE_%=:\n\t}"
                 :: "r"(mbar), "r"(parity) : "memory");
}
__device__ __forceinline__ void ldmatrix_x4(uint32_t& r0, uint32_t& r1, uint32_t& r2, uint32_t& r3, uint32_t addr) {
    asm volatile("ldmatrix.sync.aligned.m8n8.x4.shared.b16 {%0,%1,%2,%3}, [%4];\n"
                 : "=r"(r0), "=r"(r1), "=r"(r2), "=r"(r3) : "r"(addr));
}
__device__ __forceinline__ void ldmatrix_x2_trans(uint32_t& r0, uint32_t& r1, uint32_t addr) {
    asm volatile("ldmatrix.sync.aligned.m8n8.x2.trans.shared.b16 {%0,%1}, [%2];\n"
                 : "=r"(r0), "=r"(r1) : "r"(addr));
}
__device__ __forceinline__ void mma_f16acc(uint32_t c[2], const uint32_t a[4], const uint32_t b[2]) {
    asm volatile("mma.sync.aligned.m16n8k16.row.col.f16.f16.f16.f16 "
                 "{%0,%1}, {%2,%3,%4,%5}, {%6,%7}, {%0,%1};\n"
                 : "+r"(c[0]), "+r"(c[1])
                 : "r"(a[0]), "r"(a[1]), "r"(a[2]), "r"(a[3]), "r"(b[0]), "r"(b[1]));
}
__device__ __forceinline__ void mma_f32acc(float c[4], const uint32_t a[4], const uint32_t b[2]) {
    asm volatile("mma.sync.aligned.m16n8k16.row.col.f32.f16.f16.f32 "
                 "{%0,%1,%2,%3}, {%4,%5,%6,%7}, {%8,%9}, {%0,%1,%2,%3};\n"
                 : "+f"(c[0]), "+f"(c[1]), "+f"(c[2]), "+f"(c[3])
                 : "r"(a[0]), "r"(a[1]), "r"(a[2]), "r"(a[3]), "r"(b[0]), "r"(b[1]));
}
__device__ __forceinline__ float gelu_f(float v) {
    return 0.5f * v * (1.0f + erff(v * 0.7071067811865476f));
}
__device__ __forceinline__ int orig_to_win(int t) {
    int b = t >> 12, rem = t & 4095;
    int r = rem >> 6, c = rem & 63;
    int wi = (b << 6) + ((r >> 3) << 3) + (c >> 3);
    return (wi << 6) + ((r & 7) << 3) + (c & 7);
}
__device__ __forceinline__ int win_to_orig(int tw) {
    int wi = tw >> 6, k = tw & 63;
    int b = wi >> 6, w64 = wi & 63;
    int r = ((w64 >> 3) << 3) + (k >> 3);
    int c = ((w64 & 7) << 3) + (k & 7);
    return (b << 12) + (r << 6) + c;
}
__device__ __forceinline__ size_t swz_off(int row, int k, int Kd) {
    return ((size_t)((row >> 7) * (Kd >> 6) + (k >> 6)) << 14)
         + (size_t)((row & 127) * 128 + ((((k & 63) >> 3) ^ (row & 7)) << 4) + (k & 7) * 2);
}

// ---------------- fused weight convert -> swizzled fp16 tiles ----------------
__global__ void cvt_all_kernel(const float* __restrict__ wqkv, const float* __restrict__ wproj,
                               const float* __restrict__ wfc1, const float* __restrict__ wfc2,
                               __half* __restrict__ out) {
    PDL_TRIGGER();
    PDL_WAIT();
    int i = blockIdx.x * blockDim.x + threadIdx.x;
    int li = i * 8;
    const float* src; size_t basebyte; int Kd; int loc;
    if (li < WOFF_PROJ)      { src = wqkv;  loc = li;             basebyte = 0;                    Kd = 256; }
    else if (li < WOFF_FC1)  { src = wproj; loc = li - WOFF_PROJ; basebyte = (size_t)WOFF_PROJ*2;  Kd = 256; }
    else if (li < WOFF_FC2)  { src = wfc1;  loc = li - WOFF_FC1;  basebyte = (size_t)WOFF_FC1*2;   Kd = 256; }
    else                     { src = wfc2;  loc = li - WOFF_FC2;  basebyte = (size_t)WOFF_FC2*2;   Kd = 1024; }
    float4 a = *(const float4*)(src + loc);
    float4 b = *(const float4*)(src + loc + 4);
    int row = loc / Kd, k = loc % Kd;
    size_t off = basebyte + swz_off(row, k, Kd);
    __half2 p0 = __floats2half2_rn(a.x, a.y);
    __half2 p1 = __floats2half2_rn(a.z, a.w);
    __half2 p2 = __floats2half2_rn(b.x, b.y);
    __half2 p3 = __floats2half2_rn(b.z, b.w);
    uint4 pk;
    pk.x = *(uint32_t*)&p0; pk.y = *(uint32_t*)&p1; pk.z = *(uint32_t*)&p2; pk.w = *(uint32_t*)&p3;
    *(uint4*)((char*)out + off) = pk;
}

// ---------------- bias table precompute: g_bias[h][n][m] ----------------
__global__ void bias_kernel(const float* __restrict__ btab, float* __restrict__ bout) {
    PDL_TRIGGER();
    PDL_WAIT();
    int t = blockIdx.x * blockDim.x + threadIdx.x;
    int m = t & 63, n = (t >> 6) & 63, h = t >> 12;
    int rel = ((n >> 3) - (m >> 3) + 7) * 15 + ((n & 7) - (m & 7) + 7);
    bout[t] = btab[rel * 8 + h];
}

// ---------------- LayerNorm (warp per token), templated input, optional permute ----------------
template<typename TIN, int PERM>
__global__ __launch_bounds__(256) void ln_kernel(const TIN* __restrict__ x,
                                                 const float* __restrict__ g,
                                                 const float* __restrict__ b,
                                                 __half* __restrict__ out,
                                                 int tok0) {
    PDL_TRIGGER();
    PDL_WAIT();
    int warp = tok0 + ((blockIdx.x * 256 + threadIdx.x) >> 5);
    int lane = threadIdx.x & 31;
    float v[8];
    if constexpr (sizeof(TIN) == 4) {
        const float* row = (const float*)x + (size_t)warp * DIMC + lane * 8;
        float4 v0 = *(const float4*)row;
        float4 v1 = *(const float4*)(row + 4);
        v[0] = v0.x; v[1] = v0.y; v[2] = v0.z; v[3] = v0.w;
        v[4] = v1.x; v[5] = v1.y; v[6] = v1.z; v[7] = v1.w;
    } else {
        const __half* row = (const __half*)x + (size_t)warp * DIMC + lane * 8;
        uint4 pk = *(const uint4*)row;
        float2 f0 = __half22float2(*(__half2*)&pk.x);
        float2 f1 = __half22float2(*(__half2*)&pk.y);
        float2 f2 = __half22float2(*(__half2*)&pk.z);
        float2 f3 = __half22float2(*(__half2*)&pk.w);
        v[0] = f0.x; v[1] = f0.y; v[2] = f1.x; v[3] = f1.y;
        v[4] = f2.x; v[5] = f2.y; v[6] = f3.x; v[7] = f3.y;
    }
    float s = (v[0] + v[1]) + (v[2] + v[3]) + ((v[4] + v[5]) + (v[6] + v[7]));
#pragma unroll
    for (int o = 16; o; o >>= 1) s += __shfl_xor_sync(0xffffffffu, s, o);
    float mu = s * (1.0f / 256.0f);
    float d[8];
#pragma unroll
    for (int i = 0; i < 8; i++) d[i] = v[i] - mu;
    float ss = 0.f;
#pragma unroll
    for (int i = 0; i < 8; i++) ss += d[i] * d[i];
#pragma unroll
    for (int o = 16; o; o >>= 1) ss += __shfl_xor_sync(0xffffffffu, ss, o);
    float rstd = rsqrtf(ss * (1.0f / 256.0f) + 1e-5f);
    float4 gg0 = *(const float4*)(g + lane * 8);
    float4 gg1 = *(const float4*)(g + lane * 8 + 4);
    float4 bb0 = *(const float4*)(b + lane * 8);
    float4 bb1 = *(const float4*)(b + lane * 8 + 4);
    float y[8];
    y[0] = d[0] * rstd * gg0.x + bb0.x;  y[1] = d[1] * rstd * gg0.y + bb0.y;
    y[2] = d[2] * rstd * gg0.z + bb0.z;  y[3] = d[3] * rstd * gg0.w + bb0.w;
    y[4] = d[4] * rstd * gg1.x + bb1.x;  y[5] = d[5] * rstd * gg1.y + bb1.y;
    y[6] = d[6] * rstd * gg1.z + bb1.z;  y[7] = d[7] * rstd * gg1.w + bb1.w;
    int orow = PERM ? orig_to_win(warp) : warp;
    __half2 p0 = __floats2half2_rn(y[0], y[1]);
    __half2 p1 = __floats2half2_rn(y[2], y[3]);
    __half2 p2 = __floats2half2_rn(y[4], y[5]);
    __half2 p3 = __floats2half2_rn(y[6], y[7]);
    uint4 pk;
    pk.x = *(uint32_t*)&p0; pk.y = *(uint32_t*)&p1; pk.z = *(uint32_t*)&p2; pk.w = *(uint32_t*)&p3;
    *(uint4*)((char*)out + swz_off(orow, lane * 8, 256)) = pk;
}

// ---------------- fp16 TN GEMM (f16 accumulate), bulk tile loads, M-tile offset ----------------
#define STG 32768
#define GSMEM (3 * STG + 64)

template<int N, int K, int EPI>
__global__ __launch_bounds__(256, 2) void gemm_kernel(const __half* __restrict__ A,
                                                      const __half* __restrict__ Bw,
                                                      const float* __restrict__ bias,
                                                      const float* __restrict__ resf,
                                                      const __half* __restrict__ res16,
                                                      float* __restrict__ outf,
                                                      __half* __restrict__ outb,
                                                      int mt0) {
    extern __shared__ __align__(128) uint8_t dynsm[];
    const int tid = threadIdx.x;
    const int lane = tid & 31;
    const int wid = tid >> 5;
    const int wm = wid & 3;
    const int wn = wid >> 2;
    const int mtile = mt0 + blockIdx.y;
    const int m0 = mtile * 128;
    const int n0 = blockIdx.x * 128;      // x = N (fast) for L2 A-reuse
    const uint32_t sbase = smem_u32(dynsm);
    const uint32_t mb = sbase + 3 * STG;
    constexpr int KT = K / 64;

    PDL_TRIGGER();
    if (tid == 0) { mbar_init(mb, 1); mbar_init(mb + 8, 1); mbar_init(mb + 16, 1); }
    __syncthreads();
    PDL_WAIT();

    auto issue = [&](int kt) {
        uint32_t s = (uint32_t)(kt % 3);
        uint32_t mbs = mb + s * 8;
        mbar_expect_tx(mbs, 32768u);
        const char* srcA = (const char*)A + ((size_t)mtile * KT + kt) * 16384;
        const char* srcB = (const char*)Bw + ((size_t)blockIdx.x * KT + kt) * 16384;
        bulk_g2s(sbase + s * STG, srcA, 16384u, mbs);
        bulk_g2s(sbase + s * STG + 16384u, srcB, 16384u, mbs);
    };
    if (tid == 0) { issue(0); issue(1); }

    uint32_t acc[2][8][2];
#pragma unroll
    for (int a = 0; a < 2; a++)
#pragma unroll
        for (int bq = 0; bq < 8; bq++) { acc[a][bq][0] = 0u; acc[a][bq][1] = 0u; }

    const int ti = lane >> 3, rr = lane & 7;
#pragma unroll 1
    for (int kt = 0; kt < KT; kt++) {
        __syncthreads();
        if (tid == 0 && kt + 2 < KT) issue(kt + 2);
        mbar_wait(mb + (uint32_t)(kt % 3) * 8, (uint32_t)((kt / 3) & 1));
        uint32_t abase = sbase + (uint32_t)(kt % 3) * STG;
        uint32_t bbase = abase + 16384;
#pragma unroll
        for (int ks = 0; ks < 4; ks++) {
            int kcb = ks * 2;
            uint32_t afr[2][4];
#pragma unroll
            for (int mt = 0; mt < 2; mt++) {
                int row = wm * 32 + mt * 16 + ((ti & 1) ? 8 : 0) + rr;
                int kc = kcb + (ti >> 1);
                uint32_t addr = abase + ((((uint32_t)row << 3) | (uint32_t)(kc ^ (row & 7))) << 4);
                ldmatrix_x4(afr[mt][0], afr[mt][1], afr[mt][2], afr[mt][3], addr);
            }
            uint32_t bfr[8][2];
#pragma unroll
            for (int ng = 0; ng < 4; ng++) {
                int row = wn * 64 + ng * 16 + ((ti >> 1) ? 8 : 0) + rr;
                int kc = kcb + (ti & 1);
                uint32_t addr = bbase + ((((uint32_t)row << 3) | (uint32_t)(kc ^ (row & 7))) << 4);
                uint32_t r0, r1, r2, r3;
                ldmatrix_x4(r0, r1, r2, r3, addr);
                bfr[2 * ng][0] = r0;     bfr[2 * ng][1] = r1;
                bfr[2 * ng + 1][0] = r2; bfr[2 * ng + 1][1] = r3;
            }
#pragma unroll
            for (int mt = 0; mt < 2; mt++)
#pragma unroll
                for (int nt = 0; nt < 8; nt++)
                    mma_f16acc(acc[mt][nt], afr[mt], bfr[nt]);
        }
    }

    int lrow = lane >> 2, lc2 = (lane & 3) * 2;
#pragma unroll
    for (int mt = 0; mt < 2; mt++) {
#pragma unroll
        for (int hh = 0; hh < 2; hh++) {
            int r = m0 + wm * 32 + mt * 16 + lrow + hh * 8;
            if constexpr (EPI == 0) {
                __half* op = outb + (size_t)r * N;
#pragma unroll
                for (int nt = 0; nt < 8; nt++) {
                    int c = n0 + wn * 64 + nt * 8 + lc2;
                    float2 bb = *(const float2*)(bias + c);
                    float2 cv = __half22float2(*(__half2*)&acc[mt][nt][hh]);
                    *(__half2*)(op + c) = __floats2half2_rn(cv.x + bb.x, cv.y + bb.y);
                }
            } else if constexpr (EPI == 2) {
#pragma unroll
                for (int nt = 0; nt < 8; nt++) {
                    int c = n0 + wn * 64 + nt * 8 + lc2;
                    float2 bb = *(const float2*)(bias + c);
                    float2 cv = __half22float2(*(__half2*)&acc[mt][nt][hh]);
                    *(__half2*)((char*)outb + swz_off(r, c, 1024)) =
                        __floats2half2_rn(gelu_f(cv.x + bb.x), gelu_f(cv.y + bb.y));
                }
            } else if constexpr (EPI == 1) {
                int torig = win_to_orig(r);
                const float* xr = resf + (size_t)torig * 256;
                __half* op = outb + (size_t)r * 256;
#pragma unroll
                for (int nt = 0; nt < 8; nt++) {
                    int c = n0 + wn * 64 + nt * 8 + lc2;
                    float2 bb = *(const float2*)(bias + c);
                    float2 cv = __half22float2(*(__half2*)&acc[mt][nt][hh]);
                    float2 xres = *(const float2*)(xr + c);
                    *(__half2*)(op + c) = __floats2half2_rn(xres.x + cv.x + bb.x,
                                                            xres.y + cv.y + bb.y);
                }
            } else {
                int torig = win_to_orig(r);
                const __half* x1r = res16 + (size_t)r * 256;
                float* op = outf + (size_t)torig * 256;
#pragma unroll
                for (int nt = 0; nt < 8; nt++) {
                    int c = n0 + wn * 64 + nt * 8 + lc2;
                    float2 bb = *(const float2*)(bias + c);
                    float2 cv = __half22float2(*(__half2*)&acc[mt][nt][hh]);
                    float2 rr2 = __half22float2(*(const __half2*)(x1r + c));
                    *(float2*)(op + c) = make_float2(rr2.x + cv.x + bb.x, rr2.y + cv.y + bb.y);
                }
            }
        }
    }
}

// ---------------- windowed attention: fp16 in, f32 accum; swizzled fp16 out ----------------
#define ATT_PITCH 1552
#define ATT_SMEM (64 * ATT_PITCH)

__global__ __launch_bounds__(256, 2) void attn_kernel(const __half* __restrict__ qkv,
                                                      const float* __restrict__ bias_pre,
                                                      __half* __restrict__ out,
                                                      int win0) {
    extern __shared__ __align__(128) uint8_t dynsm[];
    const int w = win0 + blockIdx.x;
    const int tid = threadIdx.x;
    const int h = tid >> 5, lane = tid & 31;
    const uint32_t sb = smem_u32(dynsm);
    const __half* gw = qkv + (size_t)w * 49152;

    PDL_TRIGGER();
    PDL_WAIT();
#pragma unroll
    for (int i = 0; i < 24; i++) {
        int ch = tid + i * 256;
        int r = ch / 96, c = ch % 96;
        cp_async16(sb + (uint32_t)(r * ATT_PITCH + c * 16), gw + r * 768 + c * 8);
    }
    cp_commit();
    asm volatile("cp.async.wait_group 0;\n" ::: "memory");
    __syncthreads();

    const uint32_t qbase = sb + (uint32_t)(h * 32) * 2;
    const uint32_t kbase = sb + (uint32_t)(256 + h * 32) * 2;
    const uint32_t vbase = sb + (uint32_t)(512 + h * 32) * 2;
    const float* bp = bias_pre + h * 4096;
    const float scale = 0.17677669529663688f;
    const int ti = lane >> 3, rr = lane & 7;
    const int lq = lane >> 2, lc = (lane & 3) * 2;

#pragma unroll 1
    for (int i = 0; i < 4; i++) {
        uint32_t qf[2][4];
#pragma unroll
        for (int ks = 0; ks < 2; ks++) {
            int row = i * 16 + ((ti & 1) ? 8 : 0) + rr;
            uint32_t addr = qbase + (uint32_t)(row * ATT_PITCH) + (uint32_t)((ks * 2 + (ti >> 1)) * 16);
            ldmatrix_x4(qf[ks][0], qf[ks][1], qf[ks][2], qf[ks][3], addr);
        }
        float sacc[8][4];
#pragma unroll
        for (int j = 0; j < 8; j++)
#pragma unroll
            for (int c = 0; c < 4; c++) sacc[j][c] = 0.f;
#pragma unroll
        for (int ks = 0; ks < 2; ks++) {
#pragma unroll
            for (int ng = 0; ng < 4; ng++) {
                int row = ng * 16 + ((ti >> 1) ? 8 : 0) + rr;
                uint32_t addr = kbase + (uint32_t)(row * ATT_PITCH) + (uint32_t)((ks * 2 + (ti & 1)) * 16);
                uint32_t b0, b1, b2, b3;
                ldmatrix_x4(b0, b1, b2, b3, addr);
                uint32_t bf0[2] = { b0, b1 }, bf1[2] = { b2, b3 };
                mma_f32acc(sacc[2 * ng],     qf[ks], bf0);
                mma_f32acc(sacc[2 * ng + 1], qf[ks], bf1);
            }
        }
        int r0 = i * 16 + lq, r1 = r0 + 8;
        float p[8][4];
        float mx0 = -1e30f, mx1 = -1e30f;
#pragma unroll
        for (int j = 0; j < 8; j++) {
            float2 b0 = *(const float2*)(bp + r0 * 64 + j * 8 + lc);
            float2 b1 = *(const float2*)(bp + r1 * 64 + j * 8 + lc);
            p[j][0] = fmaf(sacc[j][0], scale, b0.x);
            p[j][1] = fmaf(sacc[j][1], scale, b0.y);
            p[j][2] = fmaf(sacc[j][2], scale, b1.x);
            p[j][3] = fmaf(sacc[j][3], scale, b1.y);
            mx0 = fmaxf(mx0, fmaxf(p[j][0], p[j][1]));
            mx1 = fmaxf(mx1, fmaxf(p[j][2], p[j][3]));
        }
        mx0 = fmaxf(mx0, __shfl_xor_sync(0xffffffffu, mx0, 1));
        mx0 = fmaxf(mx0, __shfl_xor_sync(0xffffffffu, mx0, 2));
        mx1 = fmaxf(mx1, __shfl_xor_sync(0xffffffffu, mx1, 1));
        mx1 = fmaxf(mx1, __shfl_xor_sync(0xffffffffu, mx1, 2));
        float sm0 = 0.f, sm1 = 0.f;
#pragma unroll
        for (int j = 0; j < 8; j++) {
            p[j][0] = __expf(p[j][0] - mx0);
            p[j][1] = __expf(p[j][1] - mx0);
            p[j][2] = __expf(p[j][2] - mx1);
            p[j][3] = __expf(p[j][3] - mx1);
            sm0 += p[j][0] + p[j][1];
            sm1 += p[j][2] + p[j][3];
        }
        sm0 += __shfl_xor_sync(0xffffffffu, sm0, 1);
        sm0 += __shfl_xor_sync(0xffffffffu, sm0, 2);
        sm1 += __shfl_xor_sync(0xffffffffu, sm1, 1);
        sm1 += __shfl_xor_sync(0xffffffffu, sm1, 2);
        float inv0 = 1.0f / sm0, inv1 = 1.0f / sm1;

        uint32_t ap[4][4];
#pragma unroll
        for (int ks = 0; ks < 4; ks++) {
            __half2 t0 = __floats2half2_rn(p[2 * ks][0],     p[2 * ks][1]);
            __half2 t1 = __floats2half2_rn(p[2 * ks][2],     p[2 * ks][3]);
            __half2 t2 = __floats2half2_rn(p[2 * ks + 1][0], p[2 * ks + 1][1]);
            __half2 t3 = __floats2half2_rn(p[2 * ks + 1][2], p[2 * ks + 1][3]);
            ap[ks][0] = *(uint32_t*)&t0; ap[ks][1] = *(uint32_t*)&t1;
            ap[ks][2] = *(uint32_t*)&t2; ap[ks][3] = *(uint32_t*)&t3;
        }
        float o[4][4];
#pragma unroll
        for (int jj = 0; jj < 4; jj++)
#pragma unroll
            for (int c = 0; c < 4; c++) o[jj][c] = 0.f;
#pragma unroll
        for (int ks = 0; ks < 4; ks++) {
#pragma unroll
            for (int jj = 0; jj < 4; jj++) {
                uint32_t bv[2];
                uint32_t addr = vbase + (uint32_t)((ks * 16 + (lane & 15)) * ATT_PITCH) + (uint32_t)(jj * 16);
                ldmatrix_x2_trans(bv[0], bv[1], addr);
                mma_f32acc(o[jj], ap[ks], bv);
            }
        }
        int row0 = w * 64 + r0, row1 = w * 64 + r1;
#pragma unroll
        for (int jj = 0; jj < 4; jj++) {
            int k = h * 32 + jj * 8 + lc;
            *(__half2*)((char*)out + swz_off(row0, k, 256)) =
                __floats2half2_rn(o[jj][0] * inv0, o[jj][1] * inv0);
            *(__half2*)((char*)out + swz_off(row1, k, 256)) =
                __floats2half2_rn(o[jj][2] * inv1, o[jj][3] * inv1);
        }
    }
}

// ---------------- launch: dual-stream half-pipelines with PDL ----------------
template<typename F, typename... Args>
static inline void launch_pdl(cudaStream_t st, F f, dim3 grid, dim3 block, size_t smem, Args... args) {
    cudaLaunchConfig_t cfg = {};
    cfg.gridDim = grid;
    cfg.blockDim = block;
    cfg.dynamicSmemBytes = smem;
    cfg.stream = st;
    cudaLaunchAttribute at[1];
    at[0].id = cudaLaunchAttributeProgrammaticStreamSerialization;
    at[0].val.programmaticStreamSerializationAllowed = 1;
    cfg.attrs = at;
    cfg.numAttrs = 1;
    cudaLaunchKernelEx(&cfg, f, args...);
}

extern "C" void kernel_launch(void* const* d_in, const int* in_sizes, int n_in,
                              void* d_out, int out_size) {
    const float* x      = (const float*)d_in[0];
    const float* g1     = (const float*)d_in[2];
    const float* b1     = (const float*)d_in[3];
    const float* w_qkv  = (const float*)d_in[4];
    const float* b_qkv  = (const float*)d_in[5];
    const float* btab   = (const float*)d_in[6];
    const float* w_proj = (const float*)d_in[7];
    const float* b_proj = (const float*)d_in[8];
    const float* g2     = (const float*)d_in[9];
    const float* b2     = (const float*)d_in[10];
    const float* w_fc1  = (const float*)d_in[11];
    const float* b_fc1  = (const float*)d_in[12];
    const float* w_fc2  = (const float*)d_in[13];
    const float* b_fc2  = (const float*)d_in[14];
    float* out = (float*)d_out;

    __half *xw, *qkv, *attn, *x1, *xn2, *hbuf, *wall;
    float *bpre;
    cudaGetSymbolAddress((void**)&xw,   g_xw);
    cudaGetSymbolAddress((void**)&qkv,  g_qkv);
    cudaGetSymbolAddress((void**)&attn, g_attn);
    cudaGetSymbolAddress((void**)&x1,   g_x1);
    cudaGetSymbolAddress((void**)&xn2,  g_xn2);
    cudaGetSymbolAddress((void**)&hbuf, g_h);
    cudaGetSymbolAddress((void**)&wall, g_wall);
    cudaGetSymbolAddress((void**)&bpre, g_bias);

    __half* wq = wall + WOFF_QKV;
    __half* wp = wall + WOFF_PROJ;
    __half* w1 = wall + WOFF_FC1;
    __half* w2 = wall + WOFF_FC2;

    // lazily-created side stream + fork/join events (created on the
    // correctness call, i.e. before graph capture; identical work every call)
    static cudaStream_t s1 = nullptr;
    static cudaEvent_t e0 = nullptr, e1 = nullptr;
    if (!s1) {
        cudaStreamCreateWithFlags(&s1, cudaStreamNonBlocking);
        cudaEventCreateWithFlags(&e0, cudaEventDisableTiming);
        cudaEventCreateWithFlags(&e1, cudaEventDisableTiming);
    }
    cudaStream_t s0 = 0;

    cudaFuncSetAttribute(gemm_kernel<768, 256, 0>,  cudaFuncAttributeMaxDynamicSharedMemorySize, GSMEM);
    cudaFuncSetAttribute(gemm_kernel<256, 256, 1>,  cudaFuncAttributeMaxDynamicSharedMemorySize, GSMEM);
    cudaFuncSetAttribute(gemm_kernel<1024, 256, 2>, cudaFuncAttributeMaxDynamicSharedMemorySize, GSMEM);
    cudaFuncSetAttribute(gemm_kernel<256, 1024, 3>, cudaFuncAttributeMaxDynamicSharedMemorySize, GSMEM);
    cudaFuncSetAttribute(attn_kernel, cudaFuncAttributeMaxDynamicSharedMemorySize, ATT_SMEM);

    // shared preamble on s0
    launch_pdl(s0, cvt_all_kernel, dim3(WTOT / 8 / 256), dim3(256), 0,
               w_qkv, w_proj, w_fc1, w_fc2, wall);
    launch_pdl(s0, bias_kernel, dim3(HEADS * 64 * 64 / 256), dim3(256), 0, btab, bpre);
    cudaEventRecord(e0, s0);
    cudaStreamWaitEvent(s1, e0, 0);

    // half A (tokens [0, HTOK)) on s0
    launch_pdl(s0, ln_kernel<float, 1>, dim3(HTOK / 8), dim3(256), 0, x, g1, b1, xw, 0);
    launch_pdl(s0, gemm_kernel<768, 256, 0>, dim3(6, HMT), dim3(256), (size_t)GSMEM,
               (const __half*)xw, (const __half*)wq, b_qkv,
               (const float*)nullptr, (const __half*)nullptr, (float*)nullptr, qkv, 0);
    launch_pdl(s0, attn_kernel, dim3(HTOK / 64), dim3(256), (size_t)ATT_SMEM,
               (const __half*)qkv, (const float*)bpre, attn, 0);
    launch_pdl(s0, gemm_kernel<256, 256, 1>, dim3(2, HMT), dim3(256), (size_t)GSMEM,
               (const __half*)attn, (const __half*)wp, b_proj,
               x, (const __half*)nullptr, (float*)nullptr, x1, 0);
    launch_pdl(s0, ln_kernel<__half, 0>, dim3(HTOK / 8), dim3(256), 0,
               (const __half*)x1, g2, b2, xn2, 0);
    launch_pdl(s0, gemm_kernel<1024, 256, 2>, dim3(8, HMT), dim3(256), (size_t)GSMEM,
               (const __half*)xn2, (const __half*)w1, b_fc1,
               (const float*)nullptr, (const __half*)nullptr, (float*)nullptr, hbuf, 0);
    launch_pdl(s0, gemm_kernel<256, 1024, 3>, dim3(2, HMT), dim3(256), (size_t)GSMEM,
               (const __half*)hbuf, (const __half*)w2, b_fc2,
               (const float*)nullptr, (const __half*)x1, out, (__half*)nullptr, 0);

    // half B (tokens [HTOK, TTOK)) on s1
    launch_pdl(s1, ln_kernel<float, 1>, dim3(HTOK / 8), dim3(256), 0, x, g1, b1, xw, HTOK);
    launch_pdl(s1, gemm_kernel<768, 256, 0>, dim3(6, HMT), dim3(256), (size_t)GSMEM,
               (const __half*)xw, (const __half*)wq, b_qkv,
               (const float*)nullptr, (const __half*)nullptr, (float*)nullptr, qkv, HMT);
    launch_pdl(s1, attn_kernel, dim3(HTOK / 64), dim3(256), (size_t)ATT_SMEM,
               (const __half*)qkv, (const float*)bpre, attn, HTOK / 64);
    launch_pdl(s1, gemm_kernel<256, 256, 1>, dim3(2, HMT), dim3(256), (size_t)GSMEM,
               (const __half*)attn, (const __half*)wp, b_proj,
               x, (const __half*)nullptr, (float*)nullptr, x1, HMT);
    launch_pdl(s1, ln_kernel<__half, 0>, dim3(HTOK / 8), dim3(256), 0,
               (const __half*)x1, g2, b2, xn2, HTOK);
    launch_pdl(s1, gemm_kernel<1024, 256, 2>, dim3(8, HMT), dim3(256), (size_t)GSMEM,
               (const __half*)xn2, (const __half*)w1, b_fc1,
               (const float*)nullptr, (const __half*)nullptr, (float*)nullptr, hbuf, HMT);
    launch_pdl(s1, gemm_kernel<256, 1024, 3>, dim3(2, HMT), dim3(256), (size_t)GSMEM,
               (const __half*)hbuf, (const __half*)w2, b_fc2,
               (const float*)nullptr, (const __half*)x1, out, (__half*)nullptr, HMT);
    cudaEventRecord(e1, s1);
    cudaStreamWaitEvent(s0, e1, 0);
}